// round 9
// baseline (speedup 1.0000x reference)
#include <cuda_runtime.h>
#include <cuda_bf16.h>
#include <math.h>

#define Bq 8
#define Sq 4096
#define Dq 1024
#define DCq 1024
#define Hq 16
#define NT (Bq*Sq)          // 32768 tokens

// ---------------- scratch (device globals; no allocations allowed) ----------------
// All 16-byte aligned: they are accessed through float4* in the kernels, and a
// misaligned LDG.128/STG.128 is a hardware trap (err715) on sm_103a.
__device__ __align__(16) float d_partial[512*1024];     // pool partial sums per 64-token chunk
__device__ __align__(16) float d_Sx[NT];
__device__ __align__(16) float d_Qx[NT];
__device__ __align__(16) float d_g[Bq*Dq];
__device__ __align__(16) float d_xctrl[Bq*DCq];
__device__ __align__(16) float d_emb[Bq*DCq];
__device__ __align__(16) float d_tmpA[Bq*4*DCq];
__device__ __align__(16) float d_tembed[Bq*DCq];
__device__ __align__(16) float d_condin[Bq*2*DCq];
__device__ __align__(16) float d_cond[Bq*DCq];
__device__ __align__(16) float d_mod[Bq*4*DCq];
__device__ __align__(16) float d_h[Bq*DCq];
__device__ __align__(16) float d_h3[Bq*DCq];
__device__ __align__(16) float d_zcur[Bq*DCq];
__device__ __align__(16) float d_zf[Bq*DCq];
__device__ __align__(16) float d_zfinal[Bq*DCq];
__device__ __align__(16) float d_Sz[Bq];
__device__ __align__(16) float d_Qz[Bq];
__device__ __align__(16) float d_azg[Bq*DCq];
__device__ __align__(16) float d_Wg[Dq*DCq];            // gr-scaled X-part of Wr1 (4 MB)
__device__ __align__(16) float d_AgP[64*1024];
__device__ __align__(16) float d_AbrP[64*1024];
__device__ __align__(16) float d_Ag[1024];
__device__ __align__(16) float d_Abr[1024];
__device__ __align__(16) float d_G[(size_t)NT*1024];    // gelu(u) buffer (128 MiB)

__device__ __forceinline__ float gelu_f(float x){
    return 0.5f * x * (1.0f + erff(x * 0.70710678118654752440f));
}

// block-wide (256 threads) sum + sumsq reduction; deterministic; reusable in a loop.
__device__ __forceinline__ float2 blockReduce2(float s, float q, volatile float* red, int tid){
    #pragma unroll
    for (int o = 16; o > 0; o >>= 1){
        s += __shfl_down_sync(0xffffffffu, s, o);
        q += __shfl_down_sync(0xffffffffu, q, o);
    }
    if ((tid & 31) == 0){ red[tid>>5] = s; red[8 + (tid>>5)] = q; }
    __syncthreads();
    float S = red[0]+red[1]+red[2]+red[3]+red[4]+red[5]+red[6]+red[7];
    float Q = red[8]+red[9]+red[10]+red[11]+red[12]+red[13]+red[14]+red[15];
    __syncthreads();
    return make_float2(S, Q);
}

// ---------------- 1) pool: per-token LN stats + chunk partial sums of normalized X
__global__ void k_pool(const float* __restrict__ X){
    __shared__ float red[16];
    const int chunk = blockIdx.x;          // 512 blocks = 8 batches * 64 chunks
    const int b = chunk >> 6;
    const int s0 = (chunk & 63) << 6;      // 64 tokens per chunk
    const int tid = threadIdx.x;           // 256
    float a0=0.f, a1=0.f, a2=0.f, a3=0.f;
    for (int it = 0; it < 64; it++){
        const int t = (b << 12) + s0 + it;
        float4 v = ((const float4*)(X + (size_t)t*1024))[tid];
        float s = v.x+v.y+v.z+v.w;
        float q = v.x*v.x+v.y*v.y+v.z*v.z+v.w*v.w;
        float2 r = blockReduce2(s, q, red, tid);
        if (tid == 0){ d_Sx[t] = r.x; d_Qx[t] = r.y; }
        float mu = r.x * (1.0f/1024.0f);
        float var = r.y * (1.0f/1024.0f) - mu*mu;
        float ri = rsqrtf(var + 1e-5f);
        a0 += (v.x-mu)*ri; a1 += (v.y-mu)*ri; a2 += (v.z-mu)*ri; a3 += (v.w-mu)*ri;
    }
    ((float4*)(d_partial + (size_t)chunk*1024))[tid] = make_float4(a0,a1,a2,a3);
}

__global__ void k_pool_fin(const float* __restrict__ gp, const float* __restrict__ bp){
    int i = blockIdx.x*256 + threadIdx.x;  // 8192
    if (i >= Bq*Dq) return;
    int b = i >> 10, d = i & 1023;
    float s = 0.f;
    for (int c = 0; c < 64; c++) s += d_partial[(size_t)(b*64 + c)*1024 + d];
    d_g[i] = (s * (1.0f/(float)Sq)) * gp[d] + bp[d];
}

// ---------------- 2) timestep embedding
__global__ void k_emb(const int* __restrict__ step){
    int i = blockIdx.x*256 + threadIdx.x;  // 8192
    if (i >= Bq*DCq) return;
    int j = i & (DCq-1);
    int si = *step; if (si > 31) si = 31; if (si < 0) si = 0;
    float t = (float)si / 31.0f;
    float sig = cosf(t * 1.57079632679489662f);
    if (sig < 1e-4f) sig = 1e-4f;
    const int half = DCq/2;
    int f = (j < half) ? j : j - half;
    float freq = expf(-logf(10000.0f) * (float)f / (float)half);
    float a = sig * freq;
    d_emb[i] = (j < half) ? cosf(a) : sinf(a);
}

// ---------------- 3) generic skinny GEMM: out[8,N] = act_in(A*scale)[8,K] @ W[K,N] + bias
template<int ACT_IN, int ACT_OUT>
__global__ void k_gemm8(const float* __restrict__ A, const float* __restrict__ scale,
                        const float* __restrict__ W, const float* __restrict__ bias,
                        float* __restrict__ out, int K, int N){
    __shared__ float sA[8][128];
    const int tid = threadIdx.x;                 // 128
    const int n = blockIdx.x*128 + tid;
    float acc[8] = {0,0,0,0,0,0,0,0};
    for (int kk = 0; kk < K; kk += 128){
        #pragma unroll
        for (int i = 0; i < 8; i++){
            float v = A[(size_t)i*K + kk + tid];
            if (ACT_IN) v = gelu_f(v);
            if (scale)  v *= scale[kk + tid];
            sA[i][tid] = v;
        }
        __syncthreads();
        #pragma unroll 8
        for (int k = 0; k < 128; k++){
            float w = W[(size_t)(kk + k)*N + n];
            #pragma unroll
            for (int bb = 0; bb < 8; bb++) acc[bb] += sA[bb][k]*w;
        }
        __syncthreads();
    }
    #pragma unroll
    for (int bb = 0; bb < 8; bb++){
        float v = acc[bb] + (bias ? bias[n] : 0.0f);
        if (ACT_OUT) v = gelu_f(v);
        out[(size_t)bb*N + n] = v;
    }
}

// ---------------- 4) small elementwise / LN helpers
__global__ void k_concat(){
    int i = blockIdx.x*256 + threadIdx.x;   // 16384
    if (i >= Bq*2*DCq) return;
    int b = i >> 11, k = i & 2047;
    d_condin[i] = (k < 1024) ? d_xctrl[(b<<10)+k] : d_tembed[(b<<10)+k-1024];
}

__global__ void k_copy_z(const float* __restrict__ z){
    int i = blockIdx.x*256 + threadIdx.x;   // 8192
    if (i < Bq*DCq) d_zcur[i] = z[i];
}

__global__ void k_adaln1(){
    __shared__ float red[16];
    const int b = blockIdx.x, tid = threadIdx.x;   // 8 blocks x 256
    float4 v = ((const float4*)(d_zcur + (b<<10)))[tid];
    float2 r = blockReduce2(v.x+v.y+v.z+v.w, v.x*v.x+v.y*v.y+v.z*v.z+v.w*v.w, red, tid);
    float mu = r.x*(1.0f/1024.0f);
    float ri = rsqrtf(r.y*(1.0f/1024.0f) - mu*mu + 1e-5f);
    const float* mod = d_mod + b*4096;
    int j = tid << 2;
    float4 s1 = *(const float4*)(mod + j);
    float4 h1 = *(const float4*)(mod + 1024 + j);
    float4 o;
    o.x = (v.x-mu)*ri*(1.0f+s1.x)+h1.x;
    o.y = (v.y-mu)*ri*(1.0f+s1.y)+h1.y;
    o.z = (v.z-mu)*ri*(1.0f+s1.z)+h1.z;
    o.w = (v.w-mu)*ri*(1.0f+s1.w)+h1.w;
    ((float4*)(d_h + (b<<10)))[tid] = o;
}

__global__ void k_adaln2(){
    int i = blockIdx.x*256 + threadIdx.x;   // 8192
    if (i >= Bq*DCq) return;
    int b = i >> 10, j = i & 1023;
    float s2  = d_mod[b*4096 + 2048 + j];
    float sh2 = d_mod[b*4096 + 3072 + j];
    d_zcur[i] += d_h3[i]*(1.0f+s2) + sh2;
}

__global__ void k_lnz(const float* __restrict__ gz, const float* __restrict__ bz){
    __shared__ float red[16];
    const int b = blockIdx.x, tid = threadIdx.x;
    float4 v = ((const float4*)(d_zf + (b<<10)))[tid];
    float2 r = blockReduce2(v.x+v.y+v.z+v.w, v.x*v.x+v.y*v.y+v.z*v.z+v.w*v.w, red, tid);
    float mu = r.x*(1.0f/1024.0f);
    float ri = rsqrtf(r.y*(1.0f/1024.0f) - mu*mu + 1e-5f);
    int j = tid << 2;
    float4 g4 = *(const float4*)(gz + j);
    float4 b4 = *(const float4*)(bz + j);
    float4 y;
    y.x = (v.x-mu)*ri*g4.x + b4.x;
    y.y = (v.y-mu)*ri*g4.y + b4.y;
    y.z = (v.z-mu)*ri*g4.z + b4.z;
    y.w = (v.w-mu)*ri*g4.w + b4.w;
    ((float4*)(d_zfinal + (b<<10)))[tid] = y;
    float2 r2 = blockReduce2(y.x+y.y+y.z+y.w, y.x*y.x+y.y*y.y+y.z*y.z+y.w*y.w, red, tid);
    if (tid == 0){ d_Sz[b] = r2.x; d_Qz[b] = r2.y; }
}

// ---------------- 5) router weight prep: Wg = diag(gr_x)Wr1_x ; col sums Ag, Abr
__global__ void k_prep_w(const float* __restrict__ Wr1, const float* __restrict__ gr,
                         const float* __restrict__ br){
    const int tid = threadIdx.x;            // 256, float4 over 1024 cols
    const int r0 = blockIdx.x << 5;         // 64 blocks x 32 rows
    float4 ag = make_float4(0,0,0,0), ab = make_float4(0,0,0,0);
    for (int rr = 0; rr < 32; rr++){
        int k = r0 + rr;
        float4 w = ((const float4*)(Wr1 + (size_t)k*1024))[tid];
        float gk = gr[k], bk = br[k];
        ag.x += gk*w.x; ag.y += gk*w.y; ag.z += gk*w.z; ag.w += gk*w.w;
        ab.x += bk*w.x; ab.y += bk*w.y; ab.z += bk*w.z; ab.w += bk*w.w;
        if (k < 1024)
            ((float4*)(d_Wg + (size_t)k*1024))[tid] = make_float4(gk*w.x, gk*w.y, gk*w.z, gk*w.w);
    }
    ((float4*)(d_AgP  + (size_t)blockIdx.x*1024))[tid] = ag;
    ((float4*)(d_AbrP + (size_t)blockIdx.x*1024))[tid] = ab;
}

__global__ void k_prep_w2(){
    int j = blockIdx.x*256 + threadIdx.x;
    if (j < 1024){
        float a = 0.f, c = 0.f;
        for (int p = 0; p < 64; p++){ a += d_AgP[p*1024 + j]; c += d_AbrP[p*1024 + j]; }
        d_Ag[j] = a; d_Abr[j] = c;
    }
}

// ---------------- 6) router GEMM: Y = X @ Wg, fused LN-affine fixup + gelu -> d_G
__global__ __launch_bounds__(256, 2) void k_router1(const float* __restrict__ X,
                                                    const float* __restrict__ br1){
    __shared__ float sA[8][128];
    __shared__ float sB[8][128];
    const int tid = threadIdx.x;
    const int bn = blockIdx.x;              // 0..7
    const int bm = blockIdx.y;              // 0..255
    const int tx = tid & 15;
    const int ty = tid >> 4;
    float acc[8][8];
    #pragma unroll
    for (int i = 0; i < 8; i++)
        #pragma unroll
        for (int j = 0; j < 8; j++) acc[i][j] = 0.0f;

    const int aRow = tid >> 1;
    const int aCol = (tid & 1) * 4;
    const int bRow = tid >> 5;
    const int bCol = (tid & 31) * 4;
    const float* Aptr = X + (size_t)(bm*128 + aRow)*1024 + aCol;
    const float* Bptr = d_Wg + (size_t)bRow*1024 + bn*128 + bCol;

    float4 a0 = *(const float4*)Aptr;
    float4 b0 = *(const float4*)Bptr;

    for (int kk = 0; kk < 1024; kk += 8){
        sA[aCol+0][aRow] = a0.x;
        sA[aCol+1][aRow] = a0.y;
        sA[aCol+2][aRow] = a0.z;
        sA[aCol+3][aRow] = a0.w;
        *(float4*)(&sB[bRow][bCol]) = b0;
        __syncthreads();
        if (kk + 8 < 1024){
            a0 = *(const float4*)(Aptr + (kk + 8));
            b0 = *(const float4*)(Bptr + (size_t)(kk + 8)*1024);
        }
        #pragma unroll
        for (int k = 0; k < 8; k++){
            const float4* sa4 = (const float4*)(&sA[k][0]);
            const float4* sb4 = (const float4*)(&sB[k][0]);
            float4 af0 = sa4[ty*2], af1 = sa4[ty*2+1];
            float4 bf0 = sb4[tx*2], bf1 = sb4[tx*2+1];
            float ra[8] = {af0.x,af0.y,af0.z,af0.w,af1.x,af1.y,af1.z,af1.w};
            float rb[8] = {bf0.x,bf0.y,bf0.z,bf0.w,bf1.x,bf1.y,bf1.z,bf1.w};
            #pragma unroll
            for (int i = 0; i < 8; i++)
                #pragma unroll
                for (int j = 0; j < 8; j++)
                    acc[i][j] += ra[i]*rb[j];
        }
        __syncthreads();
    }

    // epilogue: u = (Y + azg_b)*ri - mu*ri*Ag + (Abr + br1); G = gelu(u)
    const int b = (bm*128) >> 12;           // 128 | 4096 => batch constant per block
    float cz[8], cg[8], ce[8];
    #pragma unroll
    for (int j = 0; j < 8; j++){
        int jj = bn*128 + tx*8 + j;
        cz[j] = d_azg[(b<<10) + jj];
        cg[j] = d_Ag[jj];
        ce[j] = d_Abr[jj] + br1[jj];
    }
    const float Szb = d_Sz[b], Qzb = d_Qz[b];
    #pragma unroll
    for (int i = 0; i < 8; i++){
        int t = bm*128 + ty*8 + i;
        float mu  = (d_Sx[t] + Szb) * (1.0f/2048.0f);
        float var = (d_Qx[t] + Qzb) * (1.0f/2048.0f) - mu*mu;
        float ri  = rsqrtf(var + 1e-5f);
        float mri = mu * ri;
        float g[8];
        #pragma unroll
        for (int j = 0; j < 8; j++){
            float u = (acc[i][j] + cz[j])*ri - mri*cg[j] + ce[j];
            g[j] = gelu_f(u);
        }
        float* gp = d_G + (size_t)t*1024 + bn*128 + tx*8;
        *(float4*)gp       = make_float4(g[0],g[1],g[2],g[3]);
        *(float4*)(gp + 4) = make_float4(g[4],g[5],g[6],g[7]);
    }
}

// ---------------- 7) router tail: logits = G @ Wr2 + br2, softmax top-2 renorm
__global__ void k_router2(const float* __restrict__ Wr2, const float* __restrict__ br2,
                          float* __restrict__ out){
    __shared__ float sG[64][16];
    __shared__ float sW[16][16];
    __shared__ float slog[64][17];
    const int tid = threadIdx.x;            // 256
    const int h = tid & 15;
    const int slot = tid >> 4;              // 16 slots x 4 tokens
    const int t0 = blockIdx.x * 64;         // 512 blocks
    float acc[4] = {0,0,0,0};
    for (int kk = 0; kk < 1024; kk += 16){
        {
            int row = tid >> 2, c4 = (tid & 3)*4;
            *(float4*)&sG[row][c4] = *(const float4*)(d_G + (size_t)(t0+row)*1024 + kk + c4);
        }
        if (tid < 64){
            int row = tid >> 2, c4 = (tid & 3)*4;
            *(float4*)&sW[row][c4] = *(const float4*)(Wr2 + (size_t)(kk+row)*16 + c4);
        }
        __syncthreads();
        #pragma unroll
        for (int k = 0; k < 16; k++){
            float w = sW[k][h];
            #pragma unroll
            for (int i = 0; i < 4; i++) acc[i] += sG[slot*4+i][k]*w;
        }
        __syncthreads();
    }
    float bh = br2[h];
    #pragma unroll
    for (int i = 0; i < 4; i++) slog[slot*4+i][h] = acc[i] + bh;
    __syncthreads();
    if (tid < 64){
        float l[16];
        #pragma unroll
        for (int hh = 0; hh < 16; hh++) l[hh] = slog[tid][hh];
        int i1 = 0; float v1 = l[0];
        #pragma unroll
        for (int hh = 1; hh < 16; hh++) if (l[hh] > v1){ v1 = l[hh]; i1 = hh; }
        int i2 = -1; float v2 = -3.4e38f;
        #pragma unroll
        for (int hh = 0; hh < 16; hh++) if (hh != i1 && l[hh] > v2){ v2 = l[hh]; i2 = hh; }
        float e2 = expf(v2 - v1);
        float den = 1.0f + e2;
        float o1 = 1.0f/den, o2 = e2/den;
        float* op = out + (size_t)(t0 + tid)*16;
        #pragma unroll
        for (int hh = 0; hh < 16; hh++) op[hh] = (hh == i1) ? o1 : ((hh == i2) ? o2 : 0.0f);
    }
}

// ---------------- launch ----------------
static float* symPtr(const void* sym){
    void* p = nullptr;
    cudaGetSymbolAddress(&p, sym);
    return (float*)p;
}

extern "C" void kernel_launch(void* const* d_in, const int* in_sizes, int n_in,
                              void* d_out, int out_size){
    (void)in_sizes; (void)n_in; (void)out_size;
    const float* X      = (const float*)d_in[0];
    const float* z      = (const float*)d_in[1];
    const int*   step   = (const int*)  d_in[2];
    const float* g_pool = (const float*)d_in[3];
    const float* b_pool = (const float*)d_in[4];
    const float* W_inp  = (const float*)d_in[5];
    const float* b_inp  = (const float*)d_in[6];
    const float* Wt1    = (const float*)d_in[7];
    const float* bt1    = (const float*)d_in[8];
    const float* Wt2    = (const float*)d_in[9];
    const float* bt2    = (const float*)d_in[10];
    const float* Wc1    = (const float*)d_in[11];
    const float* bc1    = (const float*)d_in[12];
    const float* Wc2    = (const float*)d_in[13];
    const float* bc2    = (const float*)d_in[14];
    const float* W_mod  = (const float*)d_in[15];
    const float* b_mod  = (const float*)d_in[16];
    const float* Wm1    = (const float*)d_in[17];
    const float* bm1    = (const float*)d_in[18];
    const float* Wm2    = (const float*)d_in[19];
    const float* bm2    = (const float*)d_in[20];
    const float* Wf     = (const float*)d_in[21];
    const float* bf     = (const float*)d_in[22];
    const float* gz     = (const float*)d_in[23];
    const float* bz     = (const float*)d_in[24];
    const float* gr     = (const float*)d_in[25];
    const float* br     = (const float*)d_in[26];
    const float* Wr1    = (const float*)d_in[27];
    const float* br1    = (const float*)d_in[28];
    const float* Wr2    = (const float*)d_in[29];
    const float* br2    = (const float*)d_in[30];
    float* out = (float*)d_out;

    float* p_g      = symPtr(d_g);
    float* p_xctrl  = symPtr(d_xctrl);
    float* p_emb    = symPtr(d_emb);
    float* p_tmpA   = symPtr(d_tmpA);
    float* p_tembed = symPtr(d_tembed);
    float* p_condin = symPtr(d_condin);
    float* p_cond   = symPtr(d_cond);
    float* p_mod    = symPtr(d_mod);
    float* p_h      = symPtr(d_h);
    float* p_h3     = symPtr(d_h3);
    float* p_zcur   = symPtr(d_zcur);
    float* p_zf     = symPtr(d_zf);
    float* p_zfinal = symPtr(d_zfinal);
    float* p_azg    = symPtr(d_azg);

    // pool path (also produces per-token Sx/Qx for the router LN)
    k_pool<<<512, 256>>>(X);
    k_pool_fin<<<32, 256>>>(g_pool, b_pool);
    k_gemm8<0,0><<<8, 128>>>(p_g, nullptr, W_inp, b_inp, p_xctrl, 1024, 1024);

    // router weight prep (independent of the rest)
    k_prep_w<<<64, 256>>>(Wr1, gr, br);
    k_prep_w2<<<4, 256>>>();

    // timestep embedding MLP
    k_emb<<<32, 256>>>(step);
    k_gemm8<0,1><<<32, 128>>>(p_emb, nullptr, Wt1, bt1, p_tmpA, 1024, 4096);
    k_gemm8<0,0><<<8, 128>>>(p_tmpA, nullptr, Wt2, bt2, p_tembed, 4096, 1024);

    // cond fusion
    k_concat<<<64, 256>>>();
    k_gemm8<0,1><<<8, 128>>>(p_condin, nullptr, Wc1, bc1, p_tmpA, 2048, 1024);
    k_gemm8<0,0><<<8, 128>>>(p_tmpA, nullptr, Wc2, bc2, p_cond, 1024, 1024);

    // adaLN denoise blocks
    k_copy_z<<<32, 256>>>(z);
    for (int l = 0; l < 2; l++){
        k_gemm8<1,0><<<32, 128>>>(p_cond, nullptr, W_mod + (size_t)l*1024*4096,
                                  b_mod + (size_t)l*4096, p_mod, 1024, 4096);
        k_adaln1<<<8, 256>>>();
        k_gemm8<0,0><<<32, 128>>>(p_h, nullptr, Wm1 + (size_t)l*1024*4096,
                                  bm1 + (size_t)l*4096, p_tmpA, 1024, 4096);
        k_gemm8<1,0><<<8, 128>>>(p_tmpA, nullptr, Wm2 + (size_t)l*4096*1024,
                                 bm2 + (size_t)l*1024, p_h3, 4096, 1024);
        k_adaln2<<<32, 256>>>();
    }

    // final projection + LN (also produces Sz/Qz for router LN)
    k_gemm8<0,0><<<8, 128>>>(p_zcur, nullptr, Wf, bf, p_zf, 1024, 1024);
    k_lnz<<<8, 256>>>(gz, bz);
    // azg_b = (z_final * gr_z) @ Wr1_z
    k_gemm8<0,0><<<8, 128>>>(p_zfinal, gr + 1024, Wr1 + (size_t)1024*1024, nullptr,
                             p_azg, 1024, 1024);

    // router
    k_router1<<<dim3(8, 256, 1), 256>>>(X, br1);
    k_router2<<<512, 256>>>(Wr2, br2, out);
}

// round 11
// speedup vs baseline: 2.8032x; 2.8032x over previous
#include <cuda_runtime.h>
#include <cuda_bf16.h>
#include <math.h>

#define Bq 8
#define Sq 4096
#define Dq 1024
#define DCq 1024
#define Hq 16
#define NT (Bq*Sq)          // 32768 tokens

// ---------------- scratch (device globals; no allocations allowed) ----------------
__device__ __align__(16) float d_partial[512*1024];     // pool partial sums per 64-token chunk
__device__ __align__(16) float d_Sx[NT];
__device__ __align__(16) float d_Qx[NT];
__device__ __align__(16) float d_g[Bq*Dq];
__device__ __align__(16) float d_xctrl[Bq*DCq];
__device__ __align__(16) float d_emb[Bq*DCq];
__device__ __align__(16) float d_tmpA[Bq*4*DCq];
__device__ __align__(16) float d_tembed[Bq*DCq];
__device__ __align__(16) float d_condin[Bq*2*DCq];
__device__ __align__(16) float d_cond[Bq*DCq];
__device__ __align__(16) float d_mod[Bq*4*DCq];
__device__ __align__(16) float d_h[Bq*DCq];
__device__ __align__(16) float d_h3[Bq*DCq];
__device__ __align__(16) float d_zcur[Bq*DCq];
__device__ __align__(16) float d_zf[Bq*DCq];
__device__ __align__(16) float d_zfinal[Bq*DCq];
__device__ __align__(16) float d_Sz[Bq];
__device__ __align__(16) float d_Qz[Bq];
__device__ __align__(16) float d_azg[Bq*DCq];
__device__ __align__(16) float d_Wg[Dq*DCq];            // gr-scaled X-part of Wr1 (4 MB)
__device__ __align__(16) float d_AgP[256*1024];
__device__ __align__(16) float d_AbrP[256*1024];
__device__ __align__(16) float d_Ag[1024];
__device__ __align__(16) float d_Abr[1024];
__device__ __align__(16) float d_pp[32*8*4096];         // split-K partials (max 1 MB)
__device__ __align__(16) float d_G[(size_t)NT*1024];    // gelu(u) buffer (128 MiB)

__device__ __forceinline__ float gelu_f(float x){
    return 0.5f * x * (1.0f + erff(x * 0.70710678118654752440f));
}

// ---- packed fp32x2 helpers (Blackwell FFMA2 path; bit-identical to scalar FFMA) ----
__device__ __forceinline__ unsigned long long dup2(float x){
    unsigned long long d; unsigned int u = __float_as_uint(x);
    asm("mov.b64 %0, {%1, %1};" : "=l"(d) : "r"(u));
    return d;
}
__device__ __forceinline__ void fma2(unsigned long long &d, unsigned long long a,
                                     unsigned long long b){
    asm("fma.rn.f32x2 %0, %1, %2, %0;" : "+l"(d) : "l"(a), "l"(b));
}
union U64F2 { unsigned long long u; float2 f; };

// block-wide (256 threads) sum + sumsq reduction; deterministic.
__device__ __forceinline__ float2 blockReduce2(float s, float q, volatile float* red, int tid){
    #pragma unroll
    for (int o = 16; o > 0; o >>= 1){
        s += __shfl_down_sync(0xffffffffu, s, o);
        q += __shfl_down_sync(0xffffffffu, q, o);
    }
    if ((tid & 31) == 0){ red[tid>>5] = s; red[8 + (tid>>5)] = q; }
    __syncthreads();
    float S = red[0]+red[1]+red[2]+red[3]+red[4]+red[5]+red[6]+red[7];
    float Q = red[8]+red[9]+red[10]+red[11]+red[12]+red[13]+red[14]+red[15];
    __syncthreads();
    return make_float2(S, Q);
}

// ---------------- 1) pool: per-token LN stats + chunk partial sums of normalized X
__global__ void k_pool(const float* __restrict__ X){
    __shared__ float red[16];
    const int chunk = blockIdx.x;          // 512 blocks = 8 batches * 64 chunks
    const int b = chunk >> 6;
    const int s0 = (chunk & 63) << 6;      // 64 tokens per chunk
    const int tid = threadIdx.x;           // 256
    float a0=0.f, a1=0.f, a2=0.f, a3=0.f;
    for (int it = 0; it < 64; it++){
        const int t = (b << 12) + s0 + it;
        float4 v = ((const float4*)(X + (size_t)t*1024))[tid];
        float s = v.x+v.y+v.z+v.w;
        float q = v.x*v.x+v.y*v.y+v.z*v.z+v.w*v.w;
        float2 r = blockReduce2(s, q, red, tid);
        if (tid == 0){ d_Sx[t] = r.x; d_Qx[t] = r.y; }
        float mu = r.x * (1.0f/1024.0f);
        float var = r.y * (1.0f/1024.0f) - mu*mu;
        float ri = rsqrtf(var + 1e-5f);
        a0 += (v.x-mu)*ri; a1 += (v.y-mu)*ri; a2 += (v.z-mu)*ri; a3 += (v.w-mu)*ri;
    }
    ((float4*)(d_partial + (size_t)chunk*1024))[tid] = make_float4(a0,a1,a2,a3);
}

__global__ void k_pool_fin(const float* __restrict__ gp, const float* __restrict__ bp){
    int i = blockIdx.x*256 + threadIdx.x;  // 8192
    if (i >= Bq*Dq) return;
    int b = i >> 10, d = i & 1023;
    float s = 0.f;
    #pragma unroll 8
    for (int c = 0; c < 64; c++) s += d_partial[(size_t)(b*64 + c)*1024 + d];
    d_g[i] = (s * (1.0f/(float)Sq)) * gp[d] + bp[d];
}

// ---------------- 2) timestep embedding
__global__ void k_emb(const int* __restrict__ step){
    int i = blockIdx.x*256 + threadIdx.x;  // 8192
    if (i >= Bq*DCq) return;
    int j = i & (DCq-1);
    int si = *step; if (si > 31) si = 31; if (si < 0) si = 0;
    float t = (float)si / 31.0f;
    float sig = cosf(t * 1.57079632679489662f);
    if (sig < 1e-4f) sig = 1e-4f;
    const int half = DCq/2;
    int f = (j < half) ? j : j - half;
    float freq = expf(-logf(10000.0f) * (float)f / (float)half);
    float a = sig * freq;
    d_emb[i] = (j < half) ? cosf(a) : sinf(a);
}

// ---------------- 3) split-K skinny GEMM: part[ks][8][N] = act_in(A*scale)[8,Kc] @ W[Kc,N]
template<int ACT_IN>
__global__ void k_gemm8p(const float* __restrict__ A, const float* __restrict__ scale,
                         const float* __restrict__ W, float* __restrict__ part,
                         int K, int N, int KS){
    __shared__ float sA[8][128];
    const int tid = threadIdx.x;                 // 128
    const int n   = blockIdx.x*128 + tid;
    const int ks  = blockIdx.y;
    const int Kc  = K / KS;
    const int k0  = ks * Kc;
    // load A slab [8, Kc] with optional gelu/scale
    #pragma unroll
    for (int i = 0; i < 8; i++){
        for (int k = tid; k < Kc; k += 128){
            float v = A[(size_t)i*K + k0 + k];
            if (ACT_IN) v = gelu_f(v);
            if (scale)  v *= scale[k0 + k];
            sA[i][k] = v;
        }
    }
    __syncthreads();
    float acc[8] = {0,0,0,0,0,0,0,0};
    #pragma unroll 8
    for (int k = 0; k < Kc; k++){
        float w = W[(size_t)(k0 + k)*N + n];
        #pragma unroll
        for (int bb = 0; bb < 8; bb++) acc[bb] += sA[bb][k]*w;
    }
    float* p = part + (size_t)ks*8*N;
    #pragma unroll
    for (int bb = 0; bb < 8; bb++) p[(size_t)bb*N + n] = acc[bb];
}

template<int ACT_OUT>
__global__ void k_gemm8f(const float* __restrict__ part, const float* __restrict__ bias,
                         float* __restrict__ out, int N, int KS){
    int idx = blockIdx.x*256 + threadIdx.x;      // 8*N total
    if (idx >= 8*N) return;
    float s = 0.f;
    #pragma unroll 8
    for (int ks = 0; ks < KS; ks++) s += part[(size_t)ks*8*N + idx];
    if (bias) s += bias[idx % N];
    if (ACT_OUT) s = gelu_f(s);
    out[idx] = s;
}

// ---------------- 4) small elementwise / LN helpers
__global__ void k_concat(){
    int i = blockIdx.x*256 + threadIdx.x;   // 16384
    if (i >= Bq*2*DCq) return;
    int b = i >> 11, k = i & 2047;
    d_condin[i] = (k < 1024) ? d_xctrl[(b<<10)+k] : d_tembed[(b<<10)+k-1024];
}

__global__ void k_copy_z(const float* __restrict__ z){
    int i = blockIdx.x*256 + threadIdx.x;   // 8192
    if (i < Bq*DCq) d_zcur[i] = z[i];
}

__global__ void k_adaln1(){
    __shared__ float red[16];
    const int b = blockIdx.x, tid = threadIdx.x;   // 8 blocks x 256
    float4 v = ((const float4*)(d_zcur + (b<<10)))[tid];
    float2 r = blockReduce2(v.x+v.y+v.z+v.w, v.x*v.x+v.y*v.y+v.z*v.z+v.w*v.w, red, tid);
    float mu = r.x*(1.0f/1024.0f);
    float ri = rsqrtf(r.y*(1.0f/1024.0f) - mu*mu + 1e-5f);
    const float* mod = d_mod + b*4096;
    int j = tid << 2;
    float4 s1 = *(const float4*)(mod + j);
    float4 h1 = *(const float4*)(mod + 1024 + j);
    float4 o;
    o.x = (v.x-mu)*ri*(1.0f+s1.x)+h1.x;
    o.y = (v.y-mu)*ri*(1.0f+s1.y)+h1.y;
    o.z = (v.z-mu)*ri*(1.0f+s1.z)+h1.z;
    o.w = (v.w-mu)*ri*(1.0f+s1.w)+h1.w;
    ((float4*)(d_h + (b<<10)))[tid] = o;
}

__global__ void k_adaln2(){
    int i = blockIdx.x*256 + threadIdx.x;   // 8192
    if (i >= Bq*DCq) return;
    int b = i >> 10, j = i & 1023;
    float s2  = d_mod[b*4096 + 2048 + j];
    float sh2 = d_mod[b*4096 + 3072 + j];
    d_zcur[i] += d_h3[i]*(1.0f+s2) + sh2;
}

__global__ void k_lnz(const float* __restrict__ gz, const float* __restrict__ bz){
    __shared__ float red[16];
    const int b = blockIdx.x, tid = threadIdx.x;
    float4 v = ((const float4*)(d_zf + (b<<10)))[tid];
    float2 r = blockReduce2(v.x+v.y+v.z+v.w, v.x*v.x+v.y*v.y+v.z*v.z+v.w*v.w, red, tid);
    float mu = r.x*(1.0f/1024.0f);
    float ri = rsqrtf(r.y*(1.0f/1024.0f) - mu*mu + 1e-5f);
    int j = tid << 2;
    float4 g4 = *(const float4*)(gz + j);
    float4 b4 = *(const float4*)(bz + j);
    float4 y;
    y.x = (v.x-mu)*ri*g4.x + b4.x;
    y.y = (v.y-mu)*ri*g4.y + b4.y;
    y.z = (v.z-mu)*ri*g4.z + b4.z;
    y.w = (v.w-mu)*ri*g4.w + b4.w;
    ((float4*)(d_zfinal + (b<<10)))[tid] = y;
    float2 r2 = blockReduce2(y.x+y.y+y.z+y.w, y.x*y.x+y.y*y.y+y.z*y.z+y.w*y.w, red, tid);
    if (tid == 0){ d_Sz[b] = r2.x; d_Qz[b] = r2.y; }
}

// ---------------- 5) router weight prep: Wg = diag(gr_x)Wr1_x ; col sums Ag, Abr
__global__ void k_prep_w(const float* __restrict__ Wr1, const float* __restrict__ gr,
                         const float* __restrict__ br){
    const int tid = threadIdx.x;            // 256, float4 over 1024 cols
    const int r0 = blockIdx.x << 3;         // 256 blocks x 8 rows (2048 total)
    float4 ag = make_float4(0,0,0,0), ab = make_float4(0,0,0,0);
    #pragma unroll
    for (int rr = 0; rr < 8; rr++){
        int k = r0 + rr;
        float4 w = ((const float4*)(Wr1 + (size_t)k*1024))[tid];
        float gk = gr[k], bk = br[k];
        ag.x += gk*w.x; ag.y += gk*w.y; ag.z += gk*w.z; ag.w += gk*w.w;
        ab.x += bk*w.x; ab.y += bk*w.y; ab.z += bk*w.z; ab.w += bk*w.w;
        if (k < 1024)
            ((float4*)(d_Wg + (size_t)k*1024))[tid] = make_float4(gk*w.x, gk*w.y, gk*w.z, gk*w.w);
    }
    ((float4*)(d_AgP  + (size_t)blockIdx.x*1024))[tid] = ag;
    ((float4*)(d_AbrP + (size_t)blockIdx.x*1024))[tid] = ab;
}

__global__ void k_prep_w2(){
    int j = blockIdx.x*256 + threadIdx.x;
    if (j < 1024){
        float a = 0.f, c = 0.f;
        #pragma unroll 8
        for (int p = 0; p < 256; p++){ a += d_AgP[p*1024 + j]; c += d_AbrP[p*1024 + j]; }
        d_Ag[j] = a; d_Abr[j] = c;
    }
}

// ---------------- 6) router GEMM (FFMA2 / f32x2): Y = X @ Wg, fused LN fixup + gelu -> d_G
__global__ __launch_bounds__(256, 2) void k_router1(const float* __restrict__ X,
                                                    const float* __restrict__ br1){
    __shared__ float sA[16][128];
    __shared__ float sB[16][128];
    const int tid = threadIdx.x;
    const int bn = blockIdx.x;              // 0..7
    const int bm = blockIdx.y;              // 0..255
    const int tx = tid & 15;
    const int ty = tid >> 4;

    unsigned long long acc2[8][4];
    #pragma unroll
    for (int i = 0; i < 8; i++)
        #pragma unroll
        for (int p = 0; p < 4; p++) acc2[i][p] = 0ull;

    const int aRow = tid >> 1;              // 0..127
    const int aK   = (tid & 1) * 4;         // 0 or 4
    const int bRow = tid >> 4;              // 0..15
    const int bCol = (tid & 15) * 4;        // 0..60
    const float* Aptr = X + (size_t)(bm*128 + aRow)*1024 + aK;
    const float* Bptr = d_Wg + (size_t)bRow*1024 + bn*128 + bCol;

    float4 a0 = *(const float4*)(Aptr);
    float4 a1 = *(const float4*)(Aptr + 8);
    float4 b0 = *(const float4*)(Bptr);
    float4 b1 = *(const float4*)(Bptr + 64);

    for (int kk = 0; kk < 1024; kk += 16){
        sA[aK+0][aRow] = a0.x; sA[aK+1][aRow] = a0.y;
        sA[aK+2][aRow] = a0.z; sA[aK+3][aRow] = a0.w;
        sA[aK+8][aRow] = a1.x; sA[aK+9][aRow] = a1.y;
        sA[aK+10][aRow] = a1.z; sA[aK+11][aRow] = a1.w;
        *(float4*)(&sB[bRow][bCol])      = b0;
        *(float4*)(&sB[bRow][bCol + 64]) = b1;
        __syncthreads();
        if (kk + 16 < 1024){
            a0 = *(const float4*)(Aptr + kk + 16);
            a1 = *(const float4*)(Aptr + kk + 24);
            b0 = *(const float4*)(Bptr + (size_t)(kk + 16)*1024);
            b1 = *(const float4*)(Bptr + (size_t)(kk + 16)*1024 + 64);
        }
        #pragma unroll
        for (int k = 0; k < 16; k++){
            float4 af0 = *(const float4*)&sA[k][ty*8];
            float4 af1 = *(const float4*)&sA[k][ty*8 + 4];
            ulonglong2 bv0 = *(const ulonglong2*)&sB[k][tx*8];
            ulonglong2 bv1 = *(const ulonglong2*)&sB[k][tx*8 + 4];
            unsigned long long rb[4] = {bv0.x, bv0.y, bv1.x, bv1.y};
            float a[8] = {af0.x,af0.y,af0.z,af0.w,af1.x,af1.y,af1.z,af1.w};
            #pragma unroll
            for (int i = 0; i < 8; i++){
                unsigned long long ai = dup2(a[i]);
                #pragma unroll
                for (int p = 0; p < 4; p++) fma2(acc2[i][p], ai, rb[p]);
            }
        }
        __syncthreads();
    }

    // epilogue: u = (Y + azg_b)*ri - mu*ri*Ag + (Abr + br1); G = gelu(u)
    const int b = (bm*128) >> 12;           // 128 | 4096 => batch constant per block
    float cz[8], cg[8], ce[8];
    #pragma unroll
    for (int j = 0; j < 8; j++){
        int jj = bn*128 + tx*8 + j;
        cz[j] = d_azg[(b<<10) + jj];
        cg[j] = d_Ag[jj];
        ce[j] = d_Abr[jj] + br1[jj];
    }
    const float Szb = d_Sz[b], Qzb = d_Qz[b];
    #pragma unroll
    for (int i = 0; i < 8; i++){
        int t = bm*128 + ty*8 + i;
        float mu  = (d_Sx[t] + Szb) * (1.0f/2048.0f);
        float var = (d_Qx[t] + Qzb) * (1.0f/2048.0f) - mu*mu;
        float ri  = rsqrtf(var + 1e-5f);
        float mri = mu * ri;
        float accf[8];
        #pragma unroll
        for (int p = 0; p < 4; p++){
            U64F2 u; u.u = acc2[i][p];
            accf[2*p]   = u.f.x;
            accf[2*p+1] = u.f.y;
        }
        float g[8];
        #pragma unroll
        for (int j = 0; j < 8; j++){
            float u = (accf[j] + cz[j])*ri - mri*cg[j] + ce[j];
            g[j] = gelu_f(u);
        }
        float* gp = d_G + (size_t)t*1024 + bn*128 + tx*8;
        *(float4*)gp       = make_float4(g[0],g[1],g[2],g[3]);
        *(float4*)(gp + 4) = make_float4(g[4],g[5],g[6],g[7]);
    }
}

// ---------------- 7) router tail: logits = G @ Wr2 + br2, softmax top-2 renorm
__global__ void k_router2(const float* __restrict__ Wr2, const float* __restrict__ br2,
                          float* __restrict__ out){
    __shared__ float sG[64][16];
    __shared__ float sW[16][16];
    __shared__ float slog[64][17];
    const int tid = threadIdx.x;            // 256
    const int h = tid & 15;
    const int slot = tid >> 4;              // 16 slots x 4 tokens
    const int t0 = blockIdx.x * 64;         // 512 blocks
    float acc[4] = {0,0,0,0};
    for (int kk = 0; kk < 1024; kk += 16){
        {
            int row = tid >> 2, c4 = (tid & 3)*4;
            *(float4*)&sG[row][c4] = *(const float4*)(d_G + (size_t)(t0+row)*1024 + kk + c4);
        }
        if (tid < 64){
            int row = tid >> 2, c4 = (tid & 3)*4;
            *(float4*)&sW[row][c4] = *(const float4*)(Wr2 + (size_t)(kk+row)*16 + c4);
        }
        __syncthreads();
        #pragma unroll
        for (int k = 0; k < 16; k++){
            float w = sW[k][h];
            #pragma unroll
            for (int i = 0; i < 4; i++) acc[i] += sG[slot*4+i][k]*w;
        }
        __syncthreads();
    }
    float bh = br2[h];
    #pragma unroll
    for (int i = 0; i < 4; i++) slog[slot*4+i][h] = acc[i] + bh;
    __syncthreads();
    if (tid < 64){
        float l[16];
        #pragma unroll
        for (int hh = 0; hh < 16; hh++) l[hh] = slog[tid][hh];
        int i1 = 0; float v1 = l[0];
        #pragma unroll
        for (int hh = 1; hh < 16; hh++) if (l[hh] > v1){ v1 = l[hh]; i1 = hh; }
        int i2 = -1; float v2 = -3.4e38f;
        #pragma unroll
        for (int hh = 0; hh < 16; hh++) if (hh != i1 && l[hh] > v2){ v2 = l[hh]; i2 = hh; }
        float e2 = expf(v2 - v1);
        float den = 1.0f + e2;
        float o1 = 1.0f/den, o2 = e2/den;
        float* op = out + (size_t)(t0 + tid)*16;
        #pragma unroll
        for (int hh = 0; hh < 16; hh++) op[hh] = (hh == i1) ? o1 : ((hh == i2) ? o2 : 0.0f);
    }
}

// ---------------- launch ----------------
static float* symPtr(const void* sym){
    void* p = nullptr;
    cudaGetSymbolAddress(&p, sym);
    return (float*)p;
}

extern "C" void kernel_launch(void* const* d_in, const int* in_sizes, int n_in,
                              void* d_out, int out_size){
    (void)in_sizes; (void)n_in; (void)out_size;
    const float* X      = (const float*)d_in[0];
    const float* z      = (const float*)d_in[1];
    const int*   step   = (const int*)  d_in[2];
    const float* g_pool = (const float*)d_in[3];
    const float* b_pool = (const float*)d_in[4];
    const float* W_inp  = (const float*)d_in[5];
    const float* b_inp  = (const float*)d_in[6];
    const float* Wt1    = (const float*)d_in[7];
    const float* bt1    = (const float*)d_in[8];
    const float* Wt2    = (const float*)d_in[9];
    const float* bt2    = (const float*)d_in[10];
    const float* Wc1    = (const float*)d_in[11];
    const float* bc1    = (const float*)d_in[12];
    const float* Wc2    = (const float*)d_in[13];
    const float* bc2    = (const float*)d_in[14];
    const float* W_mod  = (const float*)d_in[15];
    const float* b_mod  = (const float*)d_in[16];
    const float* Wm1    = (const float*)d_in[17];
    const float* bm1    = (const float*)d_in[18];
    const float* Wm2    = (const float*)d_in[19];
    const float* bm2    = (const float*)d_in[20];
    const float* Wf     = (const float*)d_in[21];
    const float* bf     = (const float*)d_in[22];
    const float* gz     = (const float*)d_in[23];
    const float* bz     = (const float*)d_in[24];
    const float* gr     = (const float*)d_in[25];
    const float* br     = (const float*)d_in[26];
    const float* Wr1    = (const float*)d_in[27];
    const float* br1    = (const float*)d_in[28];
    const float* Wr2    = (const float*)d_in[29];
    const float* br2    = (const float*)d_in[30];
    float* out = (float*)d_out;

    float* p_g      = symPtr(d_g);
    float* p_xctrl  = symPtr(d_xctrl);
    float* p_emb    = symPtr(d_emb);
    float* p_tmpA   = symPtr(d_tmpA);
    float* p_tembed = symPtr(d_tembed);
    float* p_condin = symPtr(d_condin);
    float* p_cond   = symPtr(d_cond);
    float* p_mod    = symPtr(d_mod);
    float* p_h      = symPtr(d_h);
    float* p_h3     = symPtr(d_h3);
    float* p_zcur   = symPtr(d_zcur);
    float* p_zf     = symPtr(d_zf);
    float* p_zfinal = symPtr(d_zfinal);
    float* p_azg    = symPtr(d_azg);
    float* p_pp     = symPtr(d_pp);

    // pool path (also produces per-token Sx/Qx for the router LN)
    k_pool<<<512, 256>>>(X);
    k_pool_fin<<<32, 256>>>(g_pool, b_pool);

    // router weight prep (independent of the rest)
    k_prep_w<<<256, 256>>>(Wr1, gr, br);
    k_prep_w2<<<4, 256>>>();

    // x_ctrl = g @ W_inp + b_inp            (K=1024, N=1024, KS=32)
    k_gemm8p<0><<<dim3(8, 32), 128>>>(p_g, nullptr, W_inp, p_pp, 1024, 1024, 32);
    k_gemm8f<0><<<32, 256>>>(p_pp, b_inp, p_xctrl, 1024, 32);

    // timestep embedding MLP
    k_emb<<<32, 256>>>(step);
    // tmpA = gelu(emb @ Wt1 + bt1)          (K=1024, N=4096, KS=8)
    k_gemm8p<0><<<dim3(32, 8), 128>>>(p_emb, nullptr, Wt1, p_pp, 1024, 4096, 8);
    k_gemm8f<1><<<128, 256>>>(p_pp, bt1, p_tmpA, 4096, 8);
    // tembed = tmpA @ Wt2 + bt2             (K=4096, N=1024, KS=32)
    k_gemm8p<0><<<dim3(8, 32), 128>>>(p_tmpA, nullptr, Wt2, p_pp, 4096, 1024, 32);
    k_gemm8f<0><<<32, 256>>>(p_pp, bt2, p_tembed, 1024, 32);

    // cond fusion
    k_concat<<<64, 256>>>();
    // tmpA = gelu(condin @ Wc1 + bc1)       (K=2048, N=1024, KS=32)
    k_gemm8p<0><<<dim3(8, 32), 128>>>(p_condin, nullptr, Wc1, p_pp, 2048, 1024, 32);
    k_gemm8f<1><<<32, 256>>>(p_pp, bc1, p_tmpA, 1024, 32);
    // cond = tmpA @ Wc2 + bc2               (K=1024, N=1024, KS=32)
    k_gemm8p<0><<<dim3(8, 32), 128>>>(p_tmpA, nullptr, Wc2, p_pp, 1024, 1024, 32);
    k_gemm8f<0><<<32, 256>>>(p_pp, bc2, p_cond, 1024, 32);

    // adaLN denoise blocks
    k_copy_z<<<32, 256>>>(z);
    for (int l = 0; l < 2; l++){
        // mod = gelu(cond) @ W_mod + b_mod  (K=1024, N=4096, KS=8)
        k_gemm8p<1><<<dim3(32, 8), 128>>>(p_cond, nullptr, W_mod + (size_t)l*1024*4096,
                                          p_pp, 1024, 4096, 8);
        k_gemm8f<0><<<128, 256>>>(p_pp, b_mod + (size_t)l*4096, p_mod, 4096, 8);
        k_adaln1<<<8, 256>>>();
        // tmpA = h @ Wm1 + bm1              (K=1024, N=4096, KS=8)
        k_gemm8p<0><<<dim3(32, 8), 128>>>(p_h, nullptr, Wm1 + (size_t)l*1024*4096,
                                          p_pp, 1024, 4096, 8);
        k_gemm8f<0><<<128, 256>>>(p_pp, bm1 + (size_t)l*4096, p_tmpA, 4096, 8);
        // h3 = gelu(tmpA) @ Wm2 + bm2       (K=4096, N=1024, KS=32)
        k_gemm8p<1><<<dim3(8, 32), 128>>>(p_tmpA, nullptr, Wm2 + (size_t)l*4096*1024,
                                          p_pp, 4096, 1024, 32);
        k_gemm8f<0><<<32, 256>>>(p_pp, bm2 + (size_t)l*1024, p_h3, 1024, 32);
        k_adaln2<<<32, 256>>>();
    }

    // final projection + LN (also produces Sz/Qz for router LN)
    k_gemm8p<0><<<dim3(8, 32), 128>>>(p_zcur, nullptr, Wf, p_pp, 1024, 1024, 32);
    k_gemm8f<0><<<32, 256>>>(p_pp, bf, p_zf, 1024, 32);
    k_lnz<<<8, 256>>>(gz, bz);
    // azg_b = (z_final * gr_z) @ Wr1_z      (K=1024, N=1024, KS=32)
    k_gemm8p<0><<<dim3(8, 32), 128>>>(p_zfinal, gr + 1024, Wr1 + (size_t)1024*1024,
                                      p_pp, 1024, 1024, 32);
    k_gemm8f<0><<<32, 256>>>(p_pp, nullptr, p_azg, 1024, 32);

    // router
    k_router1<<<dim3(8, 256, 1), 256>>>(X, br1);
    k_router2<<<512, 256>>>(Wr2, br2, out);
}

// round 15
// speedup vs baseline: 3.9083x; 1.3943x over previous
#include <cuda_runtime.h>
#include <cuda_fp16.h>
#include <stdint.h>
#include <math.h>

#define Bq 8
#define Sq 4096
#define Dq 1024
#define DCq 1024
#define Hq 16
#define NT (Bq*Sq)          // 32768 tokens

// ---------------- scratch (device globals; no allocations allowed) ----------------
__device__ __align__(16) float d_partial[512*1024];
__device__ __align__(16) float d_Sx[NT];
__device__ __align__(16) float d_Qx[NT];
__device__ __align__(16) float d_g[Bq*Dq];
__device__ __align__(16) float d_xctrl[Bq*DCq];
__device__ __align__(16) float d_emb[Bq*DCq];
__device__ __align__(16) float d_tmpA[Bq*4*DCq];
__device__ __align__(16) float d_tembed[Bq*DCq];
__device__ __align__(16) float d_condin[Bq*2*DCq];
__device__ __align__(16) float d_cond[Bq*DCq];
__device__ __align__(16) float d_mod[Bq*4*DCq];
__device__ __align__(16) float d_h[Bq*DCq];
__device__ __align__(16) float d_h3[Bq*DCq];
__device__ __align__(16) float d_zcur[Bq*DCq];
__device__ __align__(16) float d_zf[Bq*DCq];
__device__ __align__(16) float d_zfinal[Bq*DCq];
__device__ __align__(16) float d_Sz[Bq];
__device__ __align__(16) float d_Qz[Bq];
__device__ __align__(16) float d_azg[Bq*DCq];
__device__ __align__(16) float d_AgP[256*1024];
__device__ __align__(16) float d_AbrP[256*1024];
__device__ __align__(16) float d_Ag[1024];
__device__ __align__(16) float d_Abr[1024];
__device__ __align__(16) float d_pp[32*8*4096];
// fp16 split operands for the HMMA router GEMM
__device__ __align__(16) __half d_Xh[(size_t)NT*1024];     // 32*x hi  (64 MB)
__device__ __align__(16) __half d_Xl[(size_t)NT*1024];     // 32*x lo  (64 MB)
__device__ __align__(16) __half d_WgTh[(size_t)1024*1024]; // (64*gr*Wr1)^T hi, [j][k]
__device__ __align__(16) __half d_WgTl[(size_t)1024*1024];
__device__ __align__(16) float d_plog[(size_t)16*NT*16];   // partial logits (32 MB)

__device__ __forceinline__ float gelu_f(float x){
    return 0.5f * x * (1.0f + erff(x * 0.70710678118654752440f));
}

// ---------------- warp-MMA helpers (baseline PTX; valid on plain sm_103) ----------------
__device__ __forceinline__ uint32_t smem_u32(const void* p){
    uint32_t a;
    asm("{ .reg .u64 t; cvta.to.shared.u64 t, %1; cvt.u32.u64 %0, t; }" : "=r"(a) : "l"(p));
    return a;
}
__device__ __forceinline__ void ldsm4(uint32_t* r, uint32_t addr){
    asm volatile("ldmatrix.sync.aligned.m8n8.x4.shared.b16 {%0,%1,%2,%3}, [%4];"
        : "=r"(r[0]), "=r"(r[1]), "=r"(r[2]), "=r"(r[3]) : "r"(addr));
}
__device__ __forceinline__ void mma16816(float* d, const uint32_t* a, const uint32_t* b){
    asm volatile(
        "mma.sync.aligned.m16n8k16.row.col.f32.f16.f16.f32 "
        "{%0,%1,%2,%3}, {%4,%5,%6,%7}, {%8,%9}, {%0,%1,%2,%3};"
        : "+f"(d[0]), "+f"(d[1]), "+f"(d[2]), "+f"(d[3])
        : "r"(a[0]), "r"(a[1]), "r"(a[2]), "r"(a[3]), "r"(b[0]), "r"(b[1]));
}

// block-wide (256 threads) sum + sumsq reduction; deterministic.
__device__ __forceinline__ float2 blockReduce2(float s, float q, volatile float* red, int tid){
    #pragma unroll
    for (int o = 16; o > 0; o >>= 1){
        s += __shfl_down_sync(0xffffffffu, s, o);
        q += __shfl_down_sync(0xffffffffu, q, o);
    }
    if ((tid & 31) == 0){ red[tid>>5] = s; red[8 + (tid>>5)] = q; }
    __syncthreads();
    float S = red[0]+red[1]+red[2]+red[3]+red[4]+red[5]+red[6]+red[7];
    float Q = red[8]+red[9]+red[10]+red[11]+red[12]+red[13]+red[14]+red[15];
    __syncthreads();
    return make_float2(S, Q);
}

// ---------------- 1) pool: per-token LN stats + fp16 hi/lo split of 32*X
__global__ void k_pool(const float* __restrict__ X){
    __shared__ float red[16];
    const int chunk = blockIdx.x;          // 512 blocks = 8 batches * 64 chunks
    const int b = chunk >> 6;
    const int s0 = (chunk & 63) << 6;
    const int tid = threadIdx.x;           // 256
    float a0=0.f, a1=0.f, a2=0.f, a3=0.f;
    for (int it = 0; it < 64; it++){
        const int t = (b << 12) + s0 + it;
        float4 v = ((const float4*)(X + (size_t)t*1024))[tid];
        float s = v.x+v.y+v.z+v.w;
        float q = v.x*v.x+v.y*v.y+v.z*v.z+v.w*v.w;
        float2 r = blockReduce2(s, q, red, tid);
        if (tid == 0){ d_Sx[t] = r.x; d_Qx[t] = r.y; }
        float mu = r.x * (1.0f/1024.0f);
        float var = r.y * (1.0f/1024.0f) - mu*mu;
        float ri = rsqrtf(var + 1e-5f);
        a0 += (v.x-mu)*ri; a1 += (v.y-mu)*ri; a2 += (v.z-mu)*ri; a3 += (v.w-mu)*ri;
        // fp16 split of 32*x (for HMMA router GEMM)
        union { __half h[4]; uint2 u; } ph, pl;
        float sx = v.x*32.f, sy = v.y*32.f, sz = v.z*32.f, sw = v.w*32.f;
        ph.h[0] = __float2half_rn(sx); pl.h[0] = __float2half_rn(sx - __half2float(ph.h[0]));
        ph.h[1] = __float2half_rn(sy); pl.h[1] = __float2half_rn(sy - __half2float(ph.h[1]));
        ph.h[2] = __float2half_rn(sz); pl.h[2] = __float2half_rn(sz - __half2float(ph.h[2]));
        ph.h[3] = __float2half_rn(sw); pl.h[3] = __float2half_rn(sw - __half2float(ph.h[3]));
        *(uint2*)(d_Xh + (size_t)t*1024 + tid*4) = ph.u;
        *(uint2*)(d_Xl + (size_t)t*1024 + tid*4) = pl.u;
    }
    ((float4*)(d_partial + (size_t)chunk*1024))[tid] = make_float4(a0,a1,a2,a3);
}

__global__ void k_pool_fin(const float* __restrict__ gp, const float* __restrict__ bp){
    int i = blockIdx.x*256 + threadIdx.x;  // 8192
    if (i >= Bq*Dq) return;
    int b = i >> 10, d = i & 1023;
    float s = 0.f;
    #pragma unroll 8
    for (int c = 0; c < 64; c++) s += d_partial[(size_t)(b*64 + c)*1024 + d];
    d_g[i] = (s * (1.0f/(float)Sq)) * gp[d] + bp[d];
}

// ---------------- 2) timestep embedding
__global__ void k_emb(const int* __restrict__ step){
    int i = blockIdx.x*256 + threadIdx.x;
    if (i >= Bq*DCq) return;
    int j = i & (DCq-1);
    int si = *step; if (si > 31) si = 31; if (si < 0) si = 0;
    float t = (float)si / 31.0f;
    float sig = cosf(t * 1.57079632679489662f);
    if (sig < 1e-4f) sig = 1e-4f;
    const int half = DCq/2;
    int f = (j < half) ? j : j - half;
    float freq = expf(-logf(10000.0f) * (float)f / (float)half);
    float a = sig * freq;
    d_emb[i] = (j < half) ? cosf(a) : sinf(a);
}

// ---------------- 3) split-K skinny GEMM
template<int ACT_IN>
__global__ void k_gemm8p(const float* __restrict__ A, const float* __restrict__ scale,
                         const float* __restrict__ W, float* __restrict__ part,
                         int K, int N, int KS){
    __shared__ float sA[8][128];
    const int tid = threadIdx.x;                 // 128
    const int n   = blockIdx.x*128 + tid;
    const int ks  = blockIdx.y;
    const int Kc  = K / KS;
    const int k0  = ks * Kc;
    #pragma unroll
    for (int i = 0; i < 8; i++){
        for (int k = tid; k < Kc; k += 128){
            float v = A[(size_t)i*K + k0 + k];
            if (ACT_IN) v = gelu_f(v);
            if (scale)  v *= scale[k0 + k];
            sA[i][k] = v;
        }
    }
    __syncthreads();
    float acc[8] = {0,0,0,0,0,0,0,0};
    #pragma unroll 8
    for (int k = 0; k < Kc; k++){
        float w = W[(size_t)(k0 + k)*N + n];
        #pragma unroll
        for (int bb = 0; bb < 8; bb++) acc[bb] += sA[bb][k]*w;
    }
    float* p = part + (size_t)ks*8*N;
    #pragma unroll
    for (int bb = 0; bb < 8; bb++) p[(size_t)bb*N + n] = acc[bb];
}

template<int ACT_OUT>
__global__ void k_gemm8f(const float* __restrict__ part, const float* __restrict__ bias,
                         float* __restrict__ out, int N, int KS){
    int idx = blockIdx.x*256 + threadIdx.x;
    if (idx >= 8*N) return;
    float s = 0.f;
    #pragma unroll 8
    for (int ks = 0; ks < KS; ks++) s += part[(size_t)ks*8*N + idx];
    if (bias) s += bias[idx % N];
    if (ACT_OUT) s = gelu_f(s);
    out[idx] = s;
}

// ---------------- 4) small elementwise / LN helpers
__global__ void k_concat(){
    int i = blockIdx.x*256 + threadIdx.x;
    if (i >= Bq*2*DCq) return;
    int b = i >> 11, k = i & 2047;
    d_condin[i] = (k < 1024) ? d_xctrl[(b<<10)+k] : d_tembed[(b<<10)+k-1024];
}

__global__ void k_copy_z(const float* __restrict__ z){
    int i = blockIdx.x*256 + threadIdx.x;
    if (i < Bq*DCq) d_zcur[i] = z[i];
}

__global__ void k_adaln1(){
    __shared__ float red[16];
    const int b = blockIdx.x, tid = threadIdx.x;
    float4 v = ((const float4*)(d_zcur + (b<<10)))[tid];
    float2 r = blockReduce2(v.x+v.y+v.z+v.w, v.x*v.x+v.y*v.y+v.z*v.z+v.w*v.w, red, tid);
    float mu = r.x*(1.0f/1024.0f);
    float ri = rsqrtf(r.y*(1.0f/1024.0f) - mu*mu + 1e-5f);
    const float* mod = d_mod + b*4096;
    int j = tid << 2;
    float4 s1 = *(const float4*)(mod + j);
    float4 h1 = *(const float4*)(mod + 1024 + j);
    float4 o;
    o.x = (v.x-mu)*ri*(1.0f+s1.x)+h1.x;
    o.y = (v.y-mu)*ri*(1.0f+s1.y)+h1.y;
    o.z = (v.z-mu)*ri*(1.0f+s1.z)+h1.z;
    o.w = (v.w-mu)*ri*(1.0f+s1.w)+h1.w;
    ((float4*)(d_h + (b<<10)))[tid] = o;
}

__global__ void k_adaln2(){
    int i = blockIdx.x*256 + threadIdx.x;
    if (i >= Bq*DCq) return;
    int b = i >> 10, j = i & 1023;
    float s2  = d_mod[b*4096 + 2048 + j];
    float sh2 = d_mod[b*4096 + 3072 + j];
    d_zcur[i] += d_h3[i]*(1.0f+s2) + sh2;
}

__global__ void k_lnz(const float* __restrict__ gz, const float* __restrict__ bz){
    __shared__ float red[16];
    const int b = blockIdx.x, tid = threadIdx.x;
    float4 v = ((const float4*)(d_zf + (b<<10)))[tid];
    float2 r = blockReduce2(v.x+v.y+v.z+v.w, v.x*v.x+v.y*v.y+v.z*v.z+v.w*v.w, red, tid);
    float mu = r.x*(1.0f/1024.0f);
    float ri = rsqrtf(r.y*(1.0f/1024.0f) - mu*mu + 1e-5f);
    int j = tid << 2;
    float4 g4 = *(const float4*)(gz + j);
    float4 b4 = *(const float4*)(bz + j);
    float4 y;
    y.x = (v.x-mu)*ri*g4.x + b4.x;
    y.y = (v.y-mu)*ri*g4.y + b4.y;
    y.z = (v.z-mu)*ri*g4.z + b4.z;
    y.w = (v.w-mu)*ri*g4.w + b4.w;
    ((float4*)(d_zfinal + (b<<10)))[tid] = y;
    float2 r2 = blockReduce2(y.x+y.y+y.z+y.w, y.x*y.x+y.y*y.y+y.z*y.z+y.w*y.w, red, tid);
    if (tid == 0){ d_Sz[b] = r2.x; d_Qz[b] = r2.y; }
}

// ---------------- 5) router weight prep: col sums Ag/Abr + fp16 split of (64*gr*Wr1_x)^T
__global__ void k_prep_w(const float* __restrict__ Wr1, const float* __restrict__ gr,
                         const float* __restrict__ br){
    const int tid = threadIdx.x;            // 256, float4 over 1024 cols (j = tid*4..+3)
    const int r0 = blockIdx.x << 3;         // 256 blocks x 8 k-rows
    float4 ag = make_float4(0,0,0,0), ab = make_float4(0,0,0,0);
    union { __half h[8]; int4 v; } wh[4], wl[4];
    #pragma unroll
    for (int rr = 0; rr < 8; rr++){
        int k = r0 + rr;
        float4 w = ((const float4*)(Wr1 + (size_t)k*1024))[tid];
        float gk = gr[k], bk = br[k];
        ag.x += gk*w.x; ag.y += gk*w.y; ag.z += gk*w.z; ag.w += gk*w.w;
        ab.x += bk*w.x; ab.y += bk*w.y; ab.z += bk*w.z; ab.w += bk*w.w;
        if (r0 < 1024){
            float s0 = 64.f*gk*w.x, s1 = 64.f*gk*w.y, s2 = 64.f*gk*w.z, s3 = 64.f*gk*w.w;
            wh[0].h[rr] = __float2half_rn(s0); wl[0].h[rr] = __float2half_rn(s0 - __half2float(wh[0].h[rr]));
            wh[1].h[rr] = __float2half_rn(s1); wl[1].h[rr] = __float2half_rn(s1 - __half2float(wh[1].h[rr]));
            wh[2].h[rr] = __float2half_rn(s2); wl[2].h[rr] = __float2half_rn(s2 - __half2float(wh[2].h[rr]));
            wh[3].h[rr] = __float2half_rn(s3); wl[3].h[rr] = __float2half_rn(s3 - __half2float(wh[3].h[rr]));
        }
    }
    if (r0 < 1024){
        #pragma unroll
        for (int jj = 0; jj < 4; jj++){
            *(int4*)(d_WgTh + (size_t)(tid*4 + jj)*1024 + r0) = wh[jj].v;
            *(int4*)(d_WgTl + (size_t)(tid*4 + jj)*1024 + r0) = wl[jj].v;
        }
    }
    ((float4*)(d_AgP  + (size_t)blockIdx.x*1024))[tid] = ag;
    ((float4*)(d_AbrP + (size_t)blockIdx.x*1024))[tid] = ab;
}

__global__ void k_prep_w2(){
    __shared__ float sa[256], sb[256];
    const int tid = threadIdx.x;            // 256; grid 32; 8 threads per output col
    const int j = blockIdx.x*32 + (tid >> 3);
    const int part = tid & 7;
    float a = 0.f, c = 0.f;
    for (int p = part; p < 256; p += 8){ a += d_AgP[p*1024 + j]; c += d_AbrP[p*1024 + j]; }
    sa[tid] = a; sb[tid] = c;
    __syncthreads();
    if (part == 0){
        float A = 0.f, C = 0.f;
        #pragma unroll
        for (int q = 0; q < 8; q++){ A += sa[tid+q]; C += sb[tid+q]; }
        d_Ag[j] = A; d_Abr[j] = C;
    }
}

// ---------------- 6) router GEMM on legacy HMMA (mma.sync m16n8k16), fp16 2-way split.
// Block tile 128(M)x128(N), K chunks of 32. 8 warps = 4(M) x 2(N); warp tile 32x64.
// acc = sum_k (32x_h+32x_l)(64w_h+64w_l) ~= 2048*Y  -> epilogue * 1/2048, LN fixup,
// gelu, then contract with this block's Wr2 slice -> partial logits d_plog[slice][t][16].
#define OFF_AH 0
#define OFF_AL 10240
#define OFF_BH 20480
#define OFF_BL 30720
#define OFF_W2 40960              // Wr2 slice [128][16] floats (8 KB)
#define OFF_CZ 49152
#define OFF_CG 49664
#define OFF_CE 50176
#define RSM_TOTAL 50688
#define LDA 40                    // halves per smem row (32 + 8 pad)

__global__ void __launch_bounds__(256, 1) k_router_mma(const float* __restrict__ br1,
                                                       const float* __restrict__ Wr2){
    extern __shared__ __align__(16) char sm[];
    const uint32_t smb = smem_u32(sm);
    const int tid   = threadIdx.x;
    const int wid   = tid >> 5;
    const int lane  = tid & 31;
    const int warpM = wid & 3;          // 0..3
    const int warpN = wid >> 2;         // 0..1
    const int jn0   = blockIdx.x * 128; // N block (0..7)
    const int t0    = blockIdx.y * 128; // M block (0..255)
    const int b     = t0 >> 12;

    // stage Wr2 slice + epilogue constants
    {
        const float* w2g = Wr2 + (size_t)jn0*16;
        float* w2s = (float*)(sm + OFF_W2);
        *(float4*)(w2s + tid*8)     = *(const float4*)(w2g + tid*8);
        *(float4*)(w2s + tid*8 + 4) = *(const float4*)(w2g + tid*8 + 4);
        if (tid < 128){
            ((float*)(sm + OFF_CZ))[tid] = d_azg[(b<<10) + jn0 + tid];
            ((float*)(sm + OFF_CG))[tid] = d_Ag[jn0 + tid];
            ((float*)(sm + OFF_CE))[tid] = d_Abr[jn0 + tid] + br1[jn0 + tid];
        }
    }

    float acc[2][8][4];
    #pragma unroll
    for (int mt = 0; mt < 2; mt++)
        #pragma unroll
        for (int nt = 0; nt < 8; nt++)
            #pragma unroll
            for (int e = 0; e < 4; e++) acc[mt][nt][e] = 0.0f;

    for (int it = 0; it < 32; it++){
        const int kk = it*32;
        __syncthreads();
        // stage A/B hi+lo [128 rows][32 halves] each, rows padded to LDA
        #pragma unroll
        for (int q = 0; q < 2; q++){
            int idx = q*256 + tid;          // 0..511
            int row = idx >> 2, c = idx & 3;
            uint32_t so = (uint32_t)(row*LDA + c*8)*2;
            size_t goA = (size_t)(t0  + row)*1024 + kk + c*8;
            size_t goB = (size_t)(jn0 + row)*1024 + kk + c*8;
            *(int4*)(sm + OFF_AH + so) = *(const int4*)(d_Xh + goA);
            *(int4*)(sm + OFF_AL + so) = *(const int4*)(d_Xl + goA);
            *(int4*)(sm + OFF_BH + so) = *(const int4*)(d_WgTh + goB);
            *(int4*)(sm + OFF_BL + so) = *(const int4*)(d_WgTl + goB);
        }
        __syncthreads();
        #pragma unroll
        for (int kh = 0; kh < 2; kh++){
            uint32_t ah[2][4], al[2][4], bh[8][2], bl[8][2];
            const int colh = (lane >> 4)*8 + kh*16;     // half offset within row
            #pragma unroll
            for (int mt = 0; mt < 2; mt++){
                uint32_t ra = (uint32_t)((warpM*32 + mt*16 + (lane & 15))*LDA + colh)*2;
                ldsm4(ah[mt], smb + OFF_AH + ra);
                ldsm4(al[mt], smb + OFF_AL + ra);
            }
            #pragma unroll
            for (int p = 0; p < 4; p++){
                uint32_t rb = (uint32_t)((warpN*64 + p*16 + (lane & 15))*LDA + colh)*2;
                uint32_t q4[4];
                ldsm4(q4, smb + OFF_BH + rb);
                bh[2*p][0] = q4[0]; bh[2*p][1] = q4[2];
                bh[2*p+1][0] = q4[1]; bh[2*p+1][1] = q4[3];
                ldsm4(q4, smb + OFF_BL + rb);
                bl[2*p][0] = q4[0]; bl[2*p][1] = q4[2];
                bl[2*p+1][0] = q4[1]; bl[2*p+1][1] = q4[3];
            }
            #pragma unroll
            for (int mt = 0; mt < 2; mt++)
                #pragma unroll
                for (int nt = 0; nt < 8; nt++){
                    mma16816(acc[mt][nt], ah[mt], bh[nt]);
                    mma16816(acc[mt][nt], ah[mt], bl[nt]);
                    mma16816(acc[mt][nt], al[mt], bh[nt]);
                }
        }
    }
    __syncthreads();   // staging smem now reused as per-warp gelu slabs

    // epilogue: u = (acc/2048 + cz)*ri - mu*ri*cg + ce ; g = gelu(u);
    // then per-warp contraction with Wr2 slice -> partial logits.
    const float INV = 1.0f/2048.0f;
    const float Szb = d_Sz[b], Qzb = d_Qz[b];
    const float* czs = (const float*)(sm + OFF_CZ);
    const float* cgs = (const float*)(sm + OFF_CG);
    const float* ces = (const float*)(sm + OFF_CE);
    float* gslab = (float*)(sm) + wid*1088;            // [16][68] floats per warp
    const int g8 = lane >> 2;                           // 0..7
    const int t2 = lane & 3;
    const int slice = blockIdx.x*2 + warpN;             // 0..15
    const float* w2s = (const float*)(sm + OFF_W2);

    #pragma unroll
    for (int mt = 0; mt < 2; mt++){
        int tA = t0 + warpM*32 + mt*16 + g8;
        int tB = tA + 8;
        float muA  = (d_Sx[tA] + Szb) * (1.0f/2048.0f);
        float riA  = rsqrtf((d_Qx[tA] + Qzb) * (1.0f/2048.0f) - muA*muA + 1e-5f);
        float mriA = muA * riA;
        float muB  = (d_Sx[tB] + Szb) * (1.0f/2048.0f);
        float riB  = rsqrtf((d_Qx[tB] + Qzb) * (1.0f/2048.0f) - muB*muB + 1e-5f);
        float mriB = muB * riB;
        #pragma unroll
        for (int nt = 0; nt < 8; nt++){
            int jl0 = warpN*64 + nt*8 + t2*2;
            float c0z = czs[jl0],   c0g = cgs[jl0],   c0e = ces[jl0];
            float c1z = czs[jl0+1], c1g = cgs[jl0+1], c1e = ces[jl0+1];
            float gA0 = gelu_f((acc[mt][nt][0]*INV + c0z)*riA - mriA*c0g + c0e);
            float gA1 = gelu_f((acc[mt][nt][1]*INV + c1z)*riA - mriA*c1g + c1e);
            float gB0 = gelu_f((acc[mt][nt][2]*INV + c0z)*riB - mriB*c0g + c0e);
            float gB1 = gelu_f((acc[mt][nt][3]*INV + c1z)*riB - mriB*c1g + c1e);
            int cl = nt*8 + t2*2;
            gslab[g8*68 + cl]       = gA0;
            gslab[g8*68 + cl + 1]   = gA1;
            gslab[(g8+8)*68 + cl]     = gB0;
            gslab[(g8+8)*68 + cl + 1] = gB1;
        }
        __syncwarp();
        // contraction: lane -> row r = lane%16, h-half hs = lane/16
        {
            int r  = lane & 15;
            int hs = lane >> 4;
            float pl[8] = {0,0,0,0,0,0,0,0};
            #pragma unroll 8
            for (int k = 0; k < 64; k++){
                float gv = gslab[r*68 + k];
                const float* w2 = w2s + (warpN*64 + k)*16 + hs*8;
                float4 wa = *(const float4*)(w2);
                float4 wb = *(const float4*)(w2 + 4);
                pl[0] += gv*wa.x; pl[1] += gv*wa.y; pl[2] += gv*wa.z; pl[3] += gv*wa.w;
                pl[4] += gv*wb.x; pl[5] += gv*wb.y; pl[6] += gv*wb.z; pl[7] += gv*wb.w;
            }
            int tok = t0 + warpM*32 + mt*16 + r;
            float* op = d_plog + ((size_t)slice*NT + tok)*16 + hs*8;
            *(float4*)op       = make_float4(pl[0], pl[1], pl[2], pl[3]);
            *(float4*)(op + 4) = make_float4(pl[4], pl[5], pl[6], pl[7]);
        }
        __syncwarp();
    }
}

// ---------------- 7) router tail: reduce partial logits, + br2, softmax top-2 renorm
__global__ void k_router2(const float* __restrict__ br2, float* __restrict__ out){
    int t = blockIdx.x*256 + threadIdx.x;   // 128 blocks
    if (t >= NT) return;
    float lg[16];
    #pragma unroll
    for (int h = 0; h < 16; h++) lg[h] = br2[h];
    #pragma unroll
    for (int s = 0; s < 16; s++){
        const float4* p = (const float4*)(d_plog + ((size_t)s*NT + t)*16);
        float4 a = p[0], bq = p[1], c = p[2], d = p[3];
        lg[0]+=a.x; lg[1]+=a.y; lg[2]+=a.z; lg[3]+=a.w;
        lg[4]+=bq.x; lg[5]+=bq.y; lg[6]+=bq.z; lg[7]+=bq.w;
        lg[8]+=c.x; lg[9]+=c.y; lg[10]+=c.z; lg[11]+=c.w;
        lg[12]+=d.x; lg[13]+=d.y; lg[14]+=d.z; lg[15]+=d.w;
    }
    int i1 = 0; float v1 = lg[0];
    #pragma unroll
    for (int h = 1; h < 16; h++) if (lg[h] > v1){ v1 = lg[h]; i1 = h; }
    int i2 = -1; float v2 = -3.4e38f;
    #pragma unroll
    for (int h = 0; h < 16; h++) if (h != i1 && lg[h] > v2){ v2 = lg[h]; i2 = h; }
    float e2 = expf(v2 - v1);
    float den = 1.0f + e2;
    float o1 = 1.0f/den, o2 = e2/den;
    float* op = out + (size_t)t*16;
    #pragma unroll
    for (int h = 0; h < 16; h++) op[h] = (h == i1) ? o1 : ((h == i2) ? o2 : 0.0f);
}

// ---------------- launch ----------------
static float* symPtr(const void* sym){
    void* p = nullptr;
    cudaGetSymbolAddress(&p, sym);
    return (float*)p;
}

extern "C" void kernel_launch(void* const* d_in, const int* in_sizes, int n_in,
                              void* d_out, int out_size){
    (void)in_sizes; (void)n_in; (void)out_size;
    const float* X      = (const float*)d_in[0];
    const float* z      = (const float*)d_in[1];
    const int*   step   = (const int*)  d_in[2];
    const float* g_pool = (const float*)d_in[3];
    const float* b_pool = (const float*)d_in[4];
    const float* W_inp  = (const float*)d_in[5];
    const float* b_inp  = (const float*)d_in[6];
    const float* Wt1    = (const float*)d_in[7];
    const float* bt1    = (const float*)d_in[8];
    const float* Wt2    = (const float*)d_in[9];
    const float* bt2    = (const float*)d_in[10];
    const float* Wc1    = (const float*)d_in[11];
    const float* bc1    = (const float*)d_in[12];
    const float* Wc2    = (const float*)d_in[13];
    const float* bc2    = (const float*)d_in[14];
    const float* W_mod  = (const float*)d_in[15];
    const float* b_mod  = (const float*)d_in[16];
    const float* Wm1    = (const float*)d_in[17];
    const float* bm1    = (const float*)d_in[18];
    const float* Wm2    = (const float*)d_in[19];
    const float* bm2    = (const float*)d_in[20];
    const float* Wf     = (const float*)d_in[21];
    const float* bf     = (const float*)d_in[22];
    const float* gz     = (const float*)d_in[23];
    const float* bz     = (const float*)d_in[24];
    const float* gr     = (const float*)d_in[25];
    const float* br     = (const float*)d_in[26];
    const float* Wr1    = (const float*)d_in[27];
    const float* br1    = (const float*)d_in[28];
    const float* Wr2    = (const float*)d_in[29];
    const float* br2    = (const float*)d_in[30];
    float* out = (float*)d_out;

    float* p_g      = symPtr(d_g);
    float* p_xctrl  = symPtr(d_xctrl);
    float* p_emb    = symPtr(d_emb);
    float* p_tmpA   = symPtr(d_tmpA);
    float* p_tembed = symPtr(d_tembed);
    float* p_condin = symPtr(d_condin);
    float* p_cond   = symPtr(d_cond);
    float* p_h      = symPtr(d_h);
    float* p_zcur   = symPtr(d_zcur);
    float* p_zf     = symPtr(d_zf);
    float* p_zfinal = symPtr(d_zfinal);
    float* p_azg    = symPtr(d_azg);
    float* p_pp     = symPtr(d_pp);

    static int smem_set = 0;
    if (!smem_set){
        cudaFuncSetAttribute(k_router_mma, cudaFuncAttributeMaxDynamicSharedMemorySize,
                             RSM_TOTAL);
        smem_set = 1;
    }

    // pool path (also produces per-token Sx/Qx + fp16 splits of X)
    k_pool<<<512, 256>>>(X);
    k_pool_fin<<<32, 256>>>(g_pool, b_pool);

    // router weight prep (independent of the rest)
    k_prep_w<<<256, 256>>>(Wr1, gr, br);
    k_prep_w2<<<32, 256>>>();

    // x_ctrl = g @ W_inp + b_inp
    k_gemm8p<0><<<dim3(8, 32), 128>>>(p_g, nullptr, W_inp, p_pp, 1024, 1024, 32);
    k_gemm8f<0><<<32, 256>>>(p_pp, b_inp, p_xctrl, 1024, 32);

    // timestep embedding MLP
    k_emb<<<32, 256>>>(step);
    k_gemm8p<0><<<dim3(32, 8), 128>>>(p_emb, nullptr, Wt1, p_pp, 1024, 4096, 8);
    k_gemm8f<1><<<128, 256>>>(p_pp, bt1, p_tmpA, 4096, 8);
    k_gemm8p<0><<<dim3(8, 32), 128>>>(p_tmpA, nullptr, Wt2, p_pp, 4096, 1024, 32);
    k_gemm8f<0><<<32, 256>>>(p_pp, bt2, p_tembed, 1024, 32);

    // cond fusion
    k_concat<<<64, 256>>>();
    k_gemm8p<0><<<dim3(8, 32), 128>>>(p_condin, nullptr, Wc1, p_pp, 2048, 1024, 32);
    k_gemm8f<1><<<32, 256>>>(p_pp, bc1, p_tmpA, 1024, 32);
    k_gemm8p<0><<<dim3(8, 32), 128>>>(p_tmpA, nullptr, Wc2, p_pp, 1024, 1024, 32);
    k_gemm8f<0><<<32, 256>>>(p_pp, bc2, p_cond, 1024, 32);

    // adaLN denoise blocks
    k_copy_z<<<32, 256>>>(z);
    for (int l = 0; l < 2; l++){
        k_gemm8p<1><<<dim3(32, 8), 128>>>(p_cond, nullptr, W_mod + (size_t)l*1024*4096,
                                          p_pp, 1024, 4096, 8);
        k_gemm8f<0><<<128, 256>>>(p_pp, b_mod + (size_t)l*4096, symPtr(d_mod), 4096, 8);
        k_adaln1<<<8, 256>>>();
        k_gemm8p<0><<<dim3(32, 8), 128>>>(p_h, nullptr, Wm1 + (size_t)l*1024*4096,
                                          p_pp, 1024, 4096, 8);
        k_gemm8f<0><<<128, 256>>>(p_pp, bm1 + (size_t)l*4096, p_tmpA, 4096, 8);
        k_gemm8p<1><<<dim3(8, 32), 128>>>(p_tmpA, nullptr, Wm2 + (size_t)l*4096*1024,
                                          p_pp, 4096, 1024, 32);
        k_gemm8f<0><<<32, 256>>>(p_pp, bm2 + (size_t)l*1024, symPtr(d_h3), 1024, 32);
        k_adaln2<<<32, 256>>>();
    }

    // final projection + LN
    k_gemm8p<0><<<dim3(8, 32), 128>>>(p_zcur, nullptr, Wf, p_pp, 1024, 1024, 32);
    k_gemm8f<0><<<32, 256>>>(p_pp, bf, p_zf, 1024, 32);
    k_lnz<<<8, 256>>>(gz, bz);
    k_gemm8p<0><<<dim3(8, 32), 128>>>(p_zfinal, gr + 1024, Wr1 + (size_t)1024*1024,
                                      p_pp, 1024, 1024, 32);
    k_gemm8f<0><<<32, 256>>>(p_pp, nullptr, p_azg, 1024, 32);

    // router: HMMA GEMM + fused LN fixup/gelu/Wr2 partials, then tiny reduce
    k_router_mma<<<dim3(8, 256), 256, RSM_TOTAL>>>(br1, Wr2);
    k_router2<<<128, 256>>>(br2, out);
}

// round 16
// speedup vs baseline: 4.4381x; 1.1356x over previous
#include <cuda_runtime.h>
#include <cuda_fp16.h>
#include <stdint.h>
#include <math.h>

#define Bq 8
#define Sq 4096
#define Dq 1024
#define DCq 1024
#define Hq 16
#define NT (Bq*Sq)          // 32768 tokens

// ---------------- scratch (device globals; no allocations allowed) ----------------
__device__ __align__(16) float d_partial[512*1024];
__device__ __align__(16) float d_Sx[NT];
__device__ __align__(16) float d_Qx[NT];
__device__ __align__(16) float d_g[Bq*Dq];
__device__ __align__(16) float d_xctrl[Bq*DCq];
__device__ __align__(16) float d_emb[Bq*DCq];
__device__ __align__(16) float d_tmpA[Bq*4*DCq];
__device__ __align__(16) float d_tembed[Bq*DCq];
__device__ __align__(16) float d_condin[Bq*2*DCq];
__device__ __align__(16) float d_cond[Bq*DCq];
__device__ __align__(16) float d_mod[Bq*4*DCq];
__device__ __align__(16) float d_h[Bq*DCq];
__device__ __align__(16) float d_h3[Bq*DCq];
__device__ __align__(16) float d_zcur[Bq*DCq];
__device__ __align__(16) float d_zf[Bq*DCq];
__device__ __align__(16) float d_zfinal[Bq*DCq];
__device__ __align__(16) float d_Sz[Bq];
__device__ __align__(16) float d_Qz[Bq];
__device__ __align__(16) float d_azg[Bq*DCq];
__device__ __align__(16) float d_AgP[256*1024];
__device__ __align__(16) float d_AbrP[256*1024];
__device__ __align__(16) float d_Ag[1024];
__device__ __align__(16) float d_Abr[1024];
__device__ __align__(16) float d_pp[32*8*4096];
// fp16 split operands for the HMMA router GEMM
__device__ __align__(16) __half d_Xh[(size_t)NT*1024];     // 32*x hi  (64 MB)
__device__ __align__(16) __half d_Xl[(size_t)NT*1024];     // 32*x lo  (64 MB)
__device__ __align__(16) __half d_WgTh[(size_t)1024*1024]; // (64*gr*Wr1)^T hi, [j][k]
__device__ __align__(16) __half d_WgTl[(size_t)1024*1024];
__device__ __align__(16) float d_plog[(size_t)16*NT*16];   // partial logits (32 MB)

__device__ __forceinline__ float gelu_f(float x){
    return 0.5f * x * (1.0f + erff(x * 0.70710678118654752440f));
}

// ---------------- warp-MMA + cp.async helpers (baseline PTX; valid on plain sm_103) ----
__device__ __forceinline__ uint32_t smem_u32(const void* p){
    uint32_t a;
    asm("{ .reg .u64 t; cvta.to.shared.u64 t, %1; cvt.u32.u64 %0, t; }" : "=r"(a) : "l"(p));
    return a;
}
__device__ __forceinline__ void ldsm4(uint32_t* r, uint32_t addr){
    asm volatile("ldmatrix.sync.aligned.m8n8.x4.shared.b16 {%0,%1,%2,%3}, [%4];"
        : "=r"(r[0]), "=r"(r[1]), "=r"(r[2]), "=r"(r[3]) : "r"(addr));
}
__device__ __forceinline__ void mma16816(float* d, const uint32_t* a, const uint32_t* b){
    asm volatile(
        "mma.sync.aligned.m16n8k16.row.col.f32.f16.f16.f32 "
        "{%0,%1,%2,%3}, {%4,%5,%6,%7}, {%8,%9}, {%0,%1,%2,%3};"
        : "+f"(d[0]), "+f"(d[1]), "+f"(d[2]), "+f"(d[3])
        : "r"(a[0]), "r"(a[1]), "r"(a[2]), "r"(a[3]), "r"(b[0]), "r"(b[1]));
}
__device__ __forceinline__ void cpa16(uint32_t dst, const void* src){
    asm volatile("cp.async.cg.shared.global [%0], [%1], 16;" :: "r"(dst), "l"(src));
}
#define CP_COMMIT() asm volatile("cp.async.commit_group;" ::: "memory")
#define CP_WAIT1()  asm volatile("cp.async.wait_group 1;" ::: "memory")

// block-wide (256 threads) sum + sumsq reduction; deterministic.
__device__ __forceinline__ float2 blockReduce2(float s, float q, volatile float* red, int tid){
    #pragma unroll
    for (int o = 16; o > 0; o >>= 1){
        s += __shfl_down_sync(0xffffffffu, s, o);
        q += __shfl_down_sync(0xffffffffu, q, o);
    }
    if ((tid & 31) == 0){ red[tid>>5] = s; red[8 + (tid>>5)] = q; }
    __syncthreads();
    float S = red[0]+red[1]+red[2]+red[3]+red[4]+red[5]+red[6]+red[7];
    float Q = red[8]+red[9]+red[10]+red[11]+red[12]+red[13]+red[14]+red[15];
    __syncthreads();
    return make_float2(S, Q);
}

// ---------------- 1) pool: per-token LN stats + fp16 hi/lo split of 32*X
__global__ void k_pool(const float* __restrict__ X){
    __shared__ float red[16];
    const int chunk = blockIdx.x;          // 512 blocks = 8 batches * 64 chunks
    const int b = chunk >> 6;
    const int s0 = (chunk & 63) << 6;
    const int tid = threadIdx.x;           // 256
    float a0=0.f, a1=0.f, a2=0.f, a3=0.f;
    for (int it = 0; it < 64; it++){
        const int t = (b << 12) + s0 + it;
        float4 v = ((const float4*)(X + (size_t)t*1024))[tid];
        float s = v.x+v.y+v.z+v.w;
        float q = v.x*v.x+v.y*v.y+v.z*v.z+v.w*v.w;
        float2 r = blockReduce2(s, q, red, tid);
        if (tid == 0){ d_Sx[t] = r.x; d_Qx[t] = r.y; }
        float mu = r.x * (1.0f/1024.0f);
        float var = r.y * (1.0f/1024.0f) - mu*mu;
        float ri = rsqrtf(var + 1e-5f);
        a0 += (v.x-mu)*ri; a1 += (v.y-mu)*ri; a2 += (v.z-mu)*ri; a3 += (v.w-mu)*ri;
        // fp16 split of 32*x (for HMMA router GEMM)
        union { __half h[4]; uint2 u; } ph, pl;
        float sx = v.x*32.f, sy = v.y*32.f, sz = v.z*32.f, sw = v.w*32.f;
        ph.h[0] = __float2half_rn(sx); pl.h[0] = __float2half_rn(sx - __half2float(ph.h[0]));
        ph.h[1] = __float2half_rn(sy); pl.h[1] = __float2half_rn(sy - __half2float(ph.h[1]));
        ph.h[2] = __float2half_rn(sz); pl.h[2] = __float2half_rn(sz - __half2float(ph.h[2]));
        ph.h[3] = __float2half_rn(sw); pl.h[3] = __float2half_rn(sw - __half2float(ph.h[3]));
        *(uint2*)(d_Xh + (size_t)t*1024 + tid*4) = ph.u;
        *(uint2*)(d_Xl + (size_t)t*1024 + tid*4) = pl.u;
    }
    ((float4*)(d_partial + (size_t)chunk*1024))[tid] = make_float4(a0,a1,a2,a3);
}

__global__ void k_pool_fin(const float* __restrict__ gp, const float* __restrict__ bp){
    int i = blockIdx.x*256 + threadIdx.x;  // 8192
    if (i >= Bq*Dq) return;
    int b = i >> 10, d = i & 1023;
    float s = 0.f;
    #pragma unroll 8
    for (int c = 0; c < 64; c++) s += d_partial[(size_t)(b*64 + c)*1024 + d];
    d_g[i] = (s * (1.0f/(float)Sq)) * gp[d] + bp[d];
}

// ---------------- 2) timestep embedding
__global__ void k_emb(const int* __restrict__ step){
    int i = blockIdx.x*256 + threadIdx.x;
    if (i >= Bq*DCq) return;
    int j = i & (DCq-1);
    int si = *step; if (si > 31) si = 31; if (si < 0) si = 0;
    float t = (float)si / 31.0f;
    float sig = cosf(t * 1.57079632679489662f);
    if (sig < 1e-4f) sig = 1e-4f;
    const int half = DCq/2;
    int f = (j < half) ? j : j - half;
    float freq = expf(-logf(10000.0f) * (float)f / (float)half);
    float a = sig * freq;
    d_emb[i] = (j < half) ? cosf(a) : sinf(a);
}

// ---------------- 3) split-K skinny GEMM
template<int ACT_IN>
__global__ void k_gemm8p(const float* __restrict__ A, const float* __restrict__ scale,
                         const float* __restrict__ W, float* __restrict__ part,
                         int K, int N, int KS){
    __shared__ float sA[8][128];
    const int tid = threadIdx.x;                 // 128
    const int n   = blockIdx.x*128 + tid;
    const int ks  = blockIdx.y;
    const int Kc  = K / KS;
    const int k0  = ks * Kc;
    #pragma unroll
    for (int i = 0; i < 8; i++){
        for (int k = tid; k < Kc; k += 128){
            float v = A[(size_t)i*K + k0 + k];
            if (ACT_IN) v = gelu_f(v);
            if (scale)  v *= scale[k0 + k];
            sA[i][k] = v;
        }
    }
    __syncthreads();
    float acc[8] = {0,0,0,0,0,0,0,0};
    #pragma unroll 8
    for (int k = 0; k < Kc; k++){
        float w = W[(size_t)(k0 + k)*N + n];
        #pragma unroll
        for (int bb = 0; bb < 8; bb++) acc[bb] += sA[bb][k]*w;
    }
    float* p = part + (size_t)ks*8*N;
    #pragma unroll
    for (int bb = 0; bb < 8; bb++) p[(size_t)bb*N + n] = acc[bb];
}

template<int ACT_OUT>
__global__ void k_gemm8f(const float* __restrict__ part, const float* __restrict__ bias,
                         float* __restrict__ out, int N, int KS){
    int idx = blockIdx.x*256 + threadIdx.x;
    if (idx >= 8*N) return;
    float s = 0.f;
    #pragma unroll 8
    for (int ks = 0; ks < KS; ks++) s += part[(size_t)ks*8*N + idx];
    if (bias) s += bias[idx % N];
    if (ACT_OUT) s = gelu_f(s);
    out[idx] = s;
}

// ---------------- 4) small elementwise / LN helpers
__global__ void k_concat(){
    int i = blockIdx.x*256 + threadIdx.x;
    if (i >= Bq*2*DCq) return;
    int b = i >> 11, k = i & 2047;
    d_condin[i] = (k < 1024) ? d_xctrl[(b<<10)+k] : d_tembed[(b<<10)+k-1024];
}

__global__ void k_copy_z(const float* __restrict__ z){
    int i = blockIdx.x*256 + threadIdx.x;
    if (i < Bq*DCq) d_zcur[i] = z[i];
}

__global__ void k_adaln1(){
    __shared__ float red[16];
    const int b = blockIdx.x, tid = threadIdx.x;
    float4 v = ((const float4*)(d_zcur + (b<<10)))[tid];
    float2 r = blockReduce2(v.x+v.y+v.z+v.w, v.x*v.x+v.y*v.y+v.z*v.z+v.w*v.w, red, tid);
    float mu = r.x*(1.0f/1024.0f);
    float ri = rsqrtf(r.y*(1.0f/1024.0f) - mu*mu + 1e-5f);
    const float* mod = d_mod + b*4096;
    int j = tid << 2;
    float4 s1 = *(const float4*)(mod + j);
    float4 h1 = *(const float4*)(mod + 1024 + j);
    float4 o;
    o.x = (v.x-mu)*ri*(1.0f+s1.x)+h1.x;
    o.y = (v.y-mu)*ri*(1.0f+s1.y)+h1.y;
    o.z = (v.z-mu)*ri*(1.0f+s1.z)+h1.z;
    o.w = (v.w-mu)*ri*(1.0f+s1.w)+h1.w;
    ((float4*)(d_h + (b<<10)))[tid] = o;
}

__global__ void k_adaln2(){
    int i = blockIdx.x*256 + threadIdx.x;
    if (i >= Bq*DCq) return;
    int b = i >> 10, j = i & 1023;
    float s2  = d_mod[b*4096 + 2048 + j];
    float sh2 = d_mod[b*4096 + 3072 + j];
    d_zcur[i] += d_h3[i]*(1.0f+s2) + sh2;
}

__global__ void k_lnz(const float* __restrict__ gz, const float* __restrict__ bz){
    __shared__ float red[16];
    const int b = blockIdx.x, tid = threadIdx.x;
    float4 v = ((const float4*)(d_zf + (b<<10)))[tid];
    float2 r = blockReduce2(v.x+v.y+v.z+v.w, v.x*v.x+v.y*v.y+v.z*v.z+v.w*v.w, red, tid);
    float mu = r.x*(1.0f/1024.0f);
    float ri = rsqrtf(r.y*(1.0f/1024.0f) - mu*mu + 1e-5f);
    int j = tid << 2;
    float4 g4 = *(const float4*)(gz + j);
    float4 b4 = *(const float4*)(bz + j);
    float4 y;
    y.x = (v.x-mu)*ri*g4.x + b4.x;
    y.y = (v.y-mu)*ri*g4.y + b4.y;
    y.z = (v.z-mu)*ri*g4.z + b4.z;
    y.w = (v.w-mu)*ri*g4.w + b4.w;
    ((float4*)(d_zfinal + (b<<10)))[tid] = y;
    float2 r2 = blockReduce2(y.x+y.y+y.z+y.w, y.x*y.x+y.y*y.y+y.z*y.z+y.w*y.w, red, tid);
    if (tid == 0){ d_Sz[b] = r2.x; d_Qz[b] = r2.y; }
}

// ---------------- 5) router weight prep: col sums Ag/Abr + fp16 split of (64*gr*Wr1_x)^T
__global__ void k_prep_w(const float* __restrict__ Wr1, const float* __restrict__ gr,
                         const float* __restrict__ br){
    const int tid = threadIdx.x;            // 256, float4 over 1024 cols (j = tid*4..+3)
    const int r0 = blockIdx.x << 3;         // 256 blocks x 8 k-rows
    float4 ag = make_float4(0,0,0,0), ab = make_float4(0,0,0,0);
    union { __half h[8]; int4 v; } wh[4], wl[4];
    #pragma unroll
    for (int rr = 0; rr < 8; rr++){
        int k = r0 + rr;
        float4 w = ((const float4*)(Wr1 + (size_t)k*1024))[tid];
        float gk = gr[k], bk = br[k];
        ag.x += gk*w.x; ag.y += gk*w.y; ag.z += gk*w.z; ag.w += gk*w.w;
        ab.x += bk*w.x; ab.y += bk*w.y; ab.z += bk*w.z; ab.w += bk*w.w;
        if (r0 < 1024){
            float s0 = 64.f*gk*w.x, s1 = 64.f*gk*w.y, s2 = 64.f*gk*w.z, s3 = 64.f*gk*w.w;
            wh[0].h[rr] = __float2half_rn(s0); wl[0].h[rr] = __float2half_rn(s0 - __half2float(wh[0].h[rr]));
            wh[1].h[rr] = __float2half_rn(s1); wl[1].h[rr] = __float2half_rn(s1 - __half2float(wh[1].h[rr]));
            wh[2].h[rr] = __float2half_rn(s2); wl[2].h[rr] = __float2half_rn(s2 - __half2float(wh[2].h[rr]));
            wh[3].h[rr] = __float2half_rn(s3); wl[3].h[rr] = __float2half_rn(s3 - __half2float(wh[3].h[rr]));
        }
    }
    if (r0 < 1024){
        #pragma unroll
        for (int jj = 0; jj < 4; jj++){
            *(int4*)(d_WgTh + (size_t)(tid*4 + jj)*1024 + r0) = wh[jj].v;
            *(int4*)(d_WgTl + (size_t)(tid*4 + jj)*1024 + r0) = wl[jj].v;
        }
    }
    ((float4*)(d_AgP  + (size_t)blockIdx.x*1024))[tid] = ag;
    ((float4*)(d_AbrP + (size_t)blockIdx.x*1024))[tid] = ab;
}

__global__ void k_prep_w2(){
    __shared__ float sa[256], sb[256];
    const int tid = threadIdx.x;            // 256; grid 32; 8 threads per output col
    const int j = blockIdx.x*32 + (tid >> 3);
    const int part = tid & 7;
    float a = 0.f, c = 0.f;
    for (int p = part; p < 256; p += 8){ a += d_AgP[p*1024 + j]; c += d_AbrP[p*1024 + j]; }
    sa[tid] = a; sb[tid] = c;
    __syncthreads();
    if (part == 0){
        float A = 0.f, C = 0.f;
        #pragma unroll
        for (int q = 0; q < 8; q++){ A += sa[tid+q]; C += sb[tid+q]; }
        d_Ag[j] = A; d_Abr[j] = C;
    }
}

// ---------------- 6) router GEMM on legacy HMMA, fp16 2-way split, cp.async 3-stage pipe.
// Block tile 128(M)x128(N), K chunks of 32. 8 warps = 4(M) x 2(N); warp tile 32x64.
// acc = sum_k (32x_h+32x_l)(64w_h+64w_l) ~= 2048*Y  -> epilogue * 1/2048, LN fixup,
// gelu, contract with Wr2 slice -> partial logits d_plog[slice][t][16].
#define LDA 40                    // halves per smem row (32 + 8 pad)
#define ARR_SZ 10240              // one operand array: 128*LDA*2 bytes
#define STAGE_SZ (4*ARR_SZ)       // 40960: AH, AL, BH, BL
#define NSTAGE 3
#define OFF_W2 (NSTAGE*STAGE_SZ)          // 122880: Wr2 slice [128][16] floats (8 KB)
#define OFF_CZ (OFF_W2 + 8192)            // 131072
#define OFF_CG (OFF_CZ + 512)
#define OFF_CE (OFF_CG + 512)
#define RSM_TOTAL (OFF_CE + 512)          // 132608

__global__ void __launch_bounds__(256, 1) k_router_mma(const float* __restrict__ br1,
                                                       const float* __restrict__ Wr2){
    extern __shared__ __align__(16) char sm[];
    const uint32_t smb = smem_u32(sm);
    const int tid   = threadIdx.x;
    const int wid   = tid >> 5;
    const int lane  = tid & 31;
    const int warpM = wid & 3;          // 0..3
    const int warpN = wid >> 2;         // 0..1
    const int jn0   = blockIdx.x * 128; // N block (0..7)
    const int t0    = blockIdx.y * 128; // M block (0..255)
    const int b     = t0 >> 12;

    // stage Wr2 slice + epilogue constants
    {
        const float* w2g = Wr2 + (size_t)jn0*16;
        float* w2s = (float*)(sm + OFF_W2);
        *(float4*)(w2s + tid*8)     = *(const float4*)(w2g + tid*8);
        *(float4*)(w2s + tid*8 + 4) = *(const float4*)(w2g + tid*8 + 4);
        if (tid < 128){
            ((float*)(sm + OFF_CZ))[tid] = d_azg[(b<<10) + jn0 + tid];
            ((float*)(sm + OFF_CG))[tid] = d_Ag[jn0 + tid];
            ((float*)(sm + OFF_CE))[tid] = d_Abr[jn0 + tid] + br1[jn0 + tid];
        }
    }

    // per-thread staging coordinates (8 cp.async of 16B per chunk)
    const int ld_r0 = tid >> 2;               // rows for q=0 / q=1: ld_r0, ld_r0+64
    const int ld_c  = (tid & 3) * 8;          // half offset within 32-half row

    float acc[2][8][4];
    #pragma unroll
    for (int mt = 0; mt < 2; mt++)
        #pragma unroll
        for (int nt = 0; nt < 8; nt++)
            #pragma unroll
            for (int e = 0; e < 4; e++) acc[mt][nt][e] = 0.0f;

    // --- pipeline prologue: issue chunks 0 and 1 ---
    #pragma unroll
    for (int pc = 0; pc < 2; pc++){
        const int kk = pc*32;
        const uint32_t sb = smb + pc*STAGE_SZ;
        #pragma unroll
        for (int q = 0; q < 2; q++){
            int row = ld_r0 + q*64;
            uint32_t so = (uint32_t)(row*LDA + ld_c)*2;
            size_t goA = (size_t)(t0  + row)*1024 + kk + ld_c;
            size_t goB = (size_t)(jn0 + row)*1024 + kk + ld_c;
            cpa16(sb + so,            d_Xh   + goA);
            cpa16(sb + ARR_SZ + so,   d_Xl   + goA);
            cpa16(sb + 2*ARR_SZ + so, d_WgTh + goB);
            cpa16(sb + 3*ARR_SZ + so, d_WgTl + goB);
        }
        CP_COMMIT();
    }

    for (int it = 0; it < 32; it++){
        CP_WAIT1();                 // group `it` complete (≤1 newer pending)
        __syncthreads();            // data visible to all; prior compute drained
        // issue chunk it+2 into buffer (it+2)%3 (freed by compute of it-1)
        if (it + 2 < 32){
            const int kk = (it+2)*32;
            const uint32_t sb = smb + ((it+2)%NSTAGE)*STAGE_SZ;
            #pragma unroll
            for (int q = 0; q < 2; q++){
                int row = ld_r0 + q*64;
                uint32_t so = (uint32_t)(row*LDA + ld_c)*2;
                size_t goA = (size_t)(t0  + row)*1024 + kk + ld_c;
                size_t goB = (size_t)(jn0 + row)*1024 + kk + ld_c;
                cpa16(sb + so,            d_Xh   + goA);
                cpa16(sb + ARR_SZ + so,   d_Xl   + goA);
                cpa16(sb + 2*ARR_SZ + so, d_WgTh + goB);
                cpa16(sb + 3*ARR_SZ + so, d_WgTl + goB);
            }
        }
        CP_COMMIT();                // commit (possibly empty) to keep group count aligned

        const uint32_t cb = smb + (it%NSTAGE)*STAGE_SZ;
        #pragma unroll
        for (int kh = 0; kh < 2; kh++){
            uint32_t ah[2][4], al[2][4], bh[8][2], bl[8][2];
            const int colh = (lane >> 4)*8 + kh*16;     // half offset within row
            #pragma unroll
            for (int mt = 0; mt < 2; mt++){
                uint32_t ra = (uint32_t)((warpM*32 + mt*16 + (lane & 15))*LDA + colh)*2;
                ldsm4(ah[mt], cb + ra);
                ldsm4(al[mt], cb + ARR_SZ + ra);
            }
            #pragma unroll
            for (int p = 0; p < 4; p++){
                uint32_t rb = (uint32_t)((warpN*64 + p*16 + (lane & 15))*LDA + colh)*2;
                uint32_t q4[4];
                ldsm4(q4, cb + 2*ARR_SZ + rb);
                bh[2*p][0] = q4[0]; bh[2*p][1] = q4[2];
                bh[2*p+1][0] = q4[1]; bh[2*p+1][1] = q4[3];
                ldsm4(q4, cb + 3*ARR_SZ + rb);
                bl[2*p][0] = q4[0]; bl[2*p][1] = q4[2];
                bl[2*p+1][0] = q4[1]; bl[2*p+1][1] = q4[3];
            }
            #pragma unroll
            for (int mt = 0; mt < 2; mt++)
                #pragma unroll
                for (int nt = 0; nt < 8; nt++){
                    mma16816(acc[mt][nt], ah[mt], bh[nt]);
                    mma16816(acc[mt][nt], ah[mt], bl[nt]);
                    mma16816(acc[mt][nt], al[mt], bh[nt]);
                }
        }
    }
    __syncthreads();   // staging smem now reused as per-warp gelu slabs

    // epilogue: u = (acc/2048 + cz)*ri - mu*ri*cg + ce ; g = gelu(u);
    // then per-warp contraction with Wr2 slice -> partial logits.
    const float INV = 1.0f/2048.0f;
    const float Szb = d_Sz[b], Qzb = d_Qz[b];
    const float* czs = (const float*)(sm + OFF_CZ);
    const float* cgs = (const float*)(sm + OFF_CG);
    const float* ces = (const float*)(sm + OFF_CE);
    float* gslab = (float*)(sm) + wid*1088;            // [16][68] floats per warp
    const int g8 = lane >> 2;                           // 0..7
    const int t2 = lane & 3;
    const int slice = blockIdx.x*2 + warpN;             // 0..15
    const float* w2s = (const float*)(sm + OFF_W2);

    #pragma unroll
    for (int mt = 0; mt < 2; mt++){
        int tA = t0 + warpM*32 + mt*16 + g8;
        int tB = tA + 8;
        float muA  = (d_Sx[tA] + Szb) * (1.0f/2048.0f);
        float riA  = rsqrtf((d_Qx[tA] + Qzb) * (1.0f/2048.0f) - muA*muA + 1e-5f);
        float mriA = muA * riA;
        float muB  = (d_Sx[tB] + Szb) * (1.0f/2048.0f);
        float riB  = rsqrtf((d_Qx[tB] + Qzb) * (1.0f/2048.0f) - muB*muB + 1e-5f);
        float mriB = muB * riB;
        #pragma unroll
        for (int nt = 0; nt < 8; nt++){
            int jl0 = warpN*64 + nt*8 + t2*2;
            float c0z = czs[jl0],   c0g = cgs[jl0],   c0e = ces[jl0];
            float c1z = czs[jl0+1], c1g = cgs[jl0+1], c1e = ces[jl0+1];
            float gA0 = gelu_f((acc[mt][nt][0]*INV + c0z)*riA - mriA*c0g + c0e);
            float gA1 = gelu_f((acc[mt][nt][1]*INV + c1z)*riA - mriA*c1g + c1e);
            float gB0 = gelu_f((acc[mt][nt][2]*INV + c0z)*riB - mriB*c0g + c0e);
            float gB1 = gelu_f((acc[mt][nt][3]*INV + c1z)*riB - mriB*c1g + c1e);
            int cl = nt*8 + t2*2;
            gslab[g8*68 + cl]       = gA0;
            gslab[g8*68 + cl + 1]   = gA1;
            gslab[(g8+8)*68 + cl]     = gB0;
            gslab[(g8+8)*68 + cl + 1] = gB1;
        }
        __syncwarp();
        // contraction: lane -> row r = lane%16, h-half hs = lane/16
        {
            int r  = lane & 15;
            int hs = lane >> 4;
            float pl[8] = {0,0,0,0,0,0,0,0};
            #pragma unroll 8
            for (int k = 0; k < 64; k++){
                float gv = gslab[r*68 + k];
                const float* w2 = w2s + (warpN*64 + k)*16 + hs*8;
                float4 wa = *(const float4*)(w2);
                float4 wb = *(const float4*)(w2 + 4);
                pl[0] += gv*wa.x; pl[1] += gv*wa.y; pl[2] += gv*wa.z; pl[3] += gv*wa.w;
                pl[4] += gv*wb.x; pl[5] += gv*wb.y; pl[6] += gv*wb.z; pl[7] += gv*wb.w;
            }
            int tok = t0 + warpM*32 + mt*16 + r;
            float* op = d_plog + ((size_t)slice*NT + tok)*16 + hs*8;
            *(float4*)op       = make_float4(pl[0], pl[1], pl[2], pl[3]);
            *(float4*)(op + 4) = make_float4(pl[4], pl[5], pl[6], pl[7]);
        }
        __syncwarp();
    }
}

// ---------------- 7) router tail: reduce partial logits, + br2, softmax top-2 renorm
__global__ void k_router2(const float* __restrict__ br2, float* __restrict__ out){
    int t = blockIdx.x*256 + threadIdx.x;   // 128 blocks
    if (t >= NT) return;
    float lg[16];
    #pragma unroll
    for (int h = 0; h < 16; h++) lg[h] = br2[h];
    #pragma unroll
    for (int s = 0; s < 16; s++){
        const float4* p = (const float4*)(d_plog + ((size_t)s*NT + t)*16);
        float4 a = p[0], bq = p[1], c = p[2], d = p[3];
        lg[0]+=a.x; lg[1]+=a.y; lg[2]+=a.z; lg[3]+=a.w;
        lg[4]+=bq.x; lg[5]+=bq.y; lg[6]+=bq.z; lg[7]+=bq.w;
        lg[8]+=c.x; lg[9]+=c.y; lg[10]+=c.z; lg[11]+=c.w;
        lg[12]+=d.x; lg[13]+=d.y; lg[14]+=d.z; lg[15]+=d.w;
    }
    int i1 = 0; float v1 = lg[0];
    #pragma unroll
    for (int h = 1; h < 16; h++) if (lg[h] > v1){ v1 = lg[h]; i1 = h; }
    int i2 = -1; float v2 = -3.4e38f;
    #pragma unroll
    for (int h = 0; h < 16; h++) if (h != i1 && lg[h] > v2){ v2 = lg[h]; i2 = h; }
    float e2 = expf(v2 - v1);
    float den = 1.0f + e2;
    float o1 = 1.0f/den, o2 = e2/den;
    float* op = out + (size_t)t*16;
    #pragma unroll
    for (int h = 0; h < 16; h++) op[h] = (h == i1) ? o1 : ((h == i2) ? o2 : 0.0f);
}

// ---------------- launch ----------------
static float* symPtr(const void* sym){
    void* p = nullptr;
    cudaGetSymbolAddress(&p, sym);
    return (float*)p;
}

extern "C" void kernel_launch(void* const* d_in, const int* in_sizes, int n_in,
                              void* d_out, int out_size){
    (void)in_sizes; (void)n_in; (void)out_size;
    const float* X      = (const float*)d_in[0];
    const float* z      = (const float*)d_in[1];
    const int*   step   = (const int*)  d_in[2];
    const float* g_pool = (const float*)d_in[3];
    const float* b_pool = (const float*)d_in[4];
    const float* W_inp  = (const float*)d_in[5];
    const float* b_inp  = (const float*)d_in[6];
    const float* Wt1    = (const float*)d_in[7];
    const float* bt1    = (const float*)d_in[8];
    const float* Wt2    = (const float*)d_in[9];
    const float* bt2    = (const float*)d_in[10];
    const float* Wc1    = (const float*)d_in[11];
    const float* bc1    = (const float*)d_in[12];
    const float* Wc2    = (const float*)d_in[13];
    const float* bc2    = (const float*)d_in[14];
    const float* W_mod  = (const float*)d_in[15];
    const float* b_mod  = (const float*)d_in[16];
    const float* Wm1    = (const float*)d_in[17];
    const float* bm1    = (const float*)d_in[18];
    const float* Wm2    = (const float*)d_in[19];
    const float* bm2    = (const float*)d_in[20];
    const float* Wf     = (const float*)d_in[21];
    const float* bf     = (const float*)d_in[22];
    const float* gz     = (const float*)d_in[23];
    const float* bz     = (const float*)d_in[24];
    const float* gr     = (const float*)d_in[25];
    const float* br     = (const float*)d_in[26];
    const float* Wr1    = (const float*)d_in[27];
    const float* br1    = (const float*)d_in[28];
    const float* Wr2    = (const float*)d_in[29];
    const float* br2    = (const float*)d_in[30];
    float* out = (float*)d_out;

    float* p_g      = symPtr(d_g);
    float* p_xctrl  = symPtr(d_xctrl);
    float* p_emb    = symPtr(d_emb);
    float* p_tmpA   = symPtr(d_tmpA);
    float* p_tembed = symPtr(d_tembed);
    float* p_condin = symPtr(d_condin);
    float* p_cond   = symPtr(d_cond);
    float* p_h      = symPtr(d_h);
    float* p_zcur   = symPtr(d_zcur);
    float* p_zf     = symPtr(d_zf);
    float* p_zfinal = symPtr(d_zfinal);
    float* p_azg    = symPtr(d_azg);
    float* p_pp     = symPtr(d_pp);

    static int smem_set = 0;
    if (!smem_set){
        cudaFuncSetAttribute(k_router_mma, cudaFuncAttributeMaxDynamicSharedMemorySize,
                             RSM_TOTAL);
        smem_set = 1;
    }

    // pool path (also produces per-token Sx/Qx + fp16 splits of X)
    k_pool<<<512, 256>>>(X);
    k_pool_fin<<<32, 256>>>(g_pool, b_pool);

    // router weight prep (independent of the rest)
    k_prep_w<<<256, 256>>>(Wr1, gr, br);
    k_prep_w2<<<32, 256>>>();

    // x_ctrl = g @ W_inp + b_inp
    k_gemm8p<0><<<dim3(8, 32), 128>>>(p_g, nullptr, W_inp, p_pp, 1024, 1024, 32);
    k_gemm8f<0><<<32, 256>>>(p_pp, b_inp, p_xctrl, 1024, 32);

    // timestep embedding MLP
    k_emb<<<32, 256>>>(step);
    k_gemm8p<0><<<dim3(32, 8), 128>>>(p_emb, nullptr, Wt1, p_pp, 1024, 4096, 8);
    k_gemm8f<1><<<128, 256>>>(p_pp, bt1, p_tmpA, 4096, 8);
    k_gemm8p<0><<<dim3(8, 32), 128>>>(p_tmpA, nullptr, Wt2, p_pp, 4096, 1024, 32);
    k_gemm8f<0><<<32, 256>>>(p_pp, bt2, p_tembed, 1024, 32);

    // cond fusion
    k_concat<<<64, 256>>>();
    k_gemm8p<0><<<dim3(8, 32), 128>>>(p_condin, nullptr, Wc1, p_pp, 2048, 1024, 32);
    k_gemm8f<1><<<32, 256>>>(p_pp, bc1, p_tmpA, 1024, 32);
    k_gemm8p<0><<<dim3(8, 32), 128>>>(p_tmpA, nullptr, Wc2, p_pp, 1024, 1024, 32);
    k_gemm8f<0><<<32, 256>>>(p_pp, bc2, p_cond, 1024, 32);

    // adaLN denoise blocks
    k_copy_z<<<32, 256>>>(z);
    for (int l = 0; l < 2; l++){
        k_gemm8p<1><<<dim3(32, 8), 128>>>(p_cond, nullptr, W_mod + (size_t)l*1024*4096,
                                          p_pp, 1024, 4096, 8);
        k_gemm8f<0><<<128, 256>>>(p_pp, b_mod + (size_t)l*4096, symPtr(d_mod), 4096, 8);
        k_adaln1<<<8, 256>>>();
        k_gemm8p<0><<<dim3(32, 8), 128>>>(p_h, nullptr, Wm1 + (size_t)l*1024*4096,
                                          p_pp, 1024, 4096, 8);
        k_gemm8f<0><<<128, 256>>>(p_pp, bm1 + (size_t)l*4096, p_tmpA, 4096, 8);
        k_gemm8p<1><<<dim3(8, 32), 128>>>(p_tmpA, nullptr, Wm2 + (size_t)l*4096*1024,
                                          p_pp, 4096, 1024, 32);
        k_gemm8f<0><<<32, 256>>>(p_pp, bm2 + (size_t)l*1024, symPtr(d_h3), 1024, 32);
        k_adaln2<<<32, 256>>>();
    }

    // final projection + LN
    k_gemm8p<0><<<dim3(8, 32), 128>>>(p_zcur, nullptr, Wf, p_pp, 1024, 1024, 32);
    k_gemm8f<0><<<32, 256>>>(p_pp, bf, p_zf, 1024, 32);
    k_lnz<<<8, 256>>>(gz, bz);
    k_gemm8p<0><<<dim3(8, 32), 128>>>(p_zfinal, gr + 1024, Wr1 + (size_t)1024*1024,
                                      p_pp, 1024, 1024, 32);
    k_gemm8f<0><<<32, 256>>>(p_pp, nullptr, p_azg, 1024, 32);

    // router: pipelined HMMA GEMM + fused LN fixup/gelu/Wr2 partials, then tiny reduce
    k_router_mma<<<dim3(8, 256), 256, RSM_TOTAL>>>(br1, Wr2);
    k_router2<<<128, 256>>>(br2, out);
}

// round 17
// speedup vs baseline: 5.2174x; 1.1756x over previous
#include <cuda_runtime.h>
#include <cuda_fp16.h>
#include <stdint.h>
#include <math.h>

#define Bq 8
#define Sq 4096
#define Dq 1024
#define DCq 1024
#define Hq 16
#define NT (Bq*Sq)          // 32768 tokens

// ---------------- scratch (device globals; no allocations allowed) ----------------
__device__ __align__(16) float d_partial[2048*1024];   // per-warp pool partials (8 MB)
__device__ __align__(16) float d_Sx[NT];
__device__ __align__(16) float d_Qx[NT];
__device__ __align__(16) float d_g[Bq*Dq];
__device__ __align__(16) float d_xctrl[Bq*DCq];
__device__ __align__(16) float d_emb[Bq*DCq];
__device__ __align__(16) float d_tmpA[Bq*4*DCq];
__device__ __align__(16) float d_tembed[Bq*DCq];
__device__ __align__(16) float d_condin[Bq*2*DCq];
__device__ __align__(16) float d_cond[Bq*DCq];
__device__ __align__(16) float d_mod[Bq*4*DCq];
__device__ __align__(16) float d_h[Bq*DCq];
__device__ __align__(16) float d_h3[Bq*DCq];
__device__ __align__(16) float d_zcur[Bq*DCq];
__device__ __align__(16) float d_zf[Bq*DCq];
__device__ __align__(16) float d_zfinal[Bq*DCq];
__device__ __align__(16) float d_Sz[Bq];
__device__ __align__(16) float d_Qz[Bq];
__device__ __align__(16) float d_azg[Bq*DCq];
__device__ __align__(16) float d_AgP[256*1024];
__device__ __align__(16) float d_AbrP[256*1024];
__device__ __align__(16) float d_Ag[1024];
__device__ __align__(16) float d_Abr[1024];
__device__ __align__(16) float d_pp[128*8*1024];       // split-K partials (4 MB)
// fp16 split operands for the HMMA router GEMM
__device__ __align__(16) __half d_Xh[(size_t)NT*1024];     // 32*x hi  (64 MB)
__device__ __align__(16) __half d_Xl[(size_t)NT*1024];     // 32*x lo  (64 MB)
__device__ __align__(16) __half d_WgTh[(size_t)1024*1024]; // (64*gr*Wr1)^T hi, [j][k]
__device__ __align__(16) __half d_WgTl[(size_t)1024*1024];
__device__ __align__(16) float d_plog[(size_t)16*NT*16];   // partial logits (32 MB)

__device__ __forceinline__ float gelu_f(float x){
    return 0.5f * x * (1.0f + erff(x * 0.70710678118654752440f));
}

// ---------------- warp-MMA + cp.async helpers (baseline PTX; valid on plain sm_103) ----
__device__ __forceinline__ uint32_t smem_u32(const void* p){
    uint32_t a;
    asm("{ .reg .u64 t; cvta.to.shared.u64 t, %1; cvt.u32.u64 %0, t; }" : "=r"(a) : "l"(p));
    return a;
}
__device__ __forceinline__ void ldsm4(uint32_t* r, uint32_t addr){
    asm volatile("ldmatrix.sync.aligned.m8n8.x4.shared.b16 {%0,%1,%2,%3}, [%4];"
        : "=r"(r[0]), "=r"(r[1]), "=r"(r[2]), "=r"(r[3]) : "r"(addr));
}
__device__ __forceinline__ void mma16816(float* d, const uint32_t* a, const uint32_t* b){
    asm volatile(
        "mma.sync.aligned.m16n8k16.row.col.f32.f16.f16.f32 "
        "{%0,%1,%2,%3}, {%4,%5,%6,%7}, {%8,%9}, {%0,%1,%2,%3};"
        : "+f"(d[0]), "+f"(d[1]), "+f"(d[2]), "+f"(d[3])
        : "r"(a[0]), "r"(a[1]), "r"(a[2]), "r"(a[3]), "r"(b[0]), "r"(b[1]));
}
__device__ __forceinline__ void cpa16(uint32_t dst, const void* src){
    asm volatile("cp.async.cg.shared.global [%0], [%1], 16;" :: "r"(dst), "l"(src));
}
#define CP_COMMIT() asm volatile("cp.async.commit_group;" ::: "memory")
#define CP_WAIT1()  asm volatile("cp.async.wait_group 1;" ::: "memory")

// ---------------- 1) pool: warp-per-token LN stats + fp16 hi/lo split of 32*X
// grid 256 x 256 threads; each warp handles 16 tokens; no block-wide syncs.
__global__ void k_pool(const float* __restrict__ X){
    const int gw   = blockIdx.x*8 + (threadIdx.x >> 5);   // 0..2047
    const int lane = threadIdx.x & 31;
    float4 acc[8];
    #pragma unroll
    for (int i = 0; i < 8; i++) acc[i] = make_float4(0.f,0.f,0.f,0.f);
    for (int it = 0; it < 16; it++){
        const int t = gw*16 + it;
        const float* xr = X + (size_t)t*1024 + lane*4;
        float4 v[8];
        float s = 0.f, q = 0.f;
        #pragma unroll
        for (int i = 0; i < 8; i++){
            v[i] = *(const float4*)(xr + i*128);
            s += v[i].x+v[i].y+v[i].z+v[i].w;
            q += v[i].x*v[i].x+v[i].y*v[i].y+v[i].z*v[i].z+v[i].w*v[i].w;
        }
        #pragma unroll
        for (int o = 16; o > 0; o >>= 1){
            s += __shfl_xor_sync(0xffffffffu, s, o);
            q += __shfl_xor_sync(0xffffffffu, q, o);
        }
        if (lane == 0){ d_Sx[t] = s; d_Qx[t] = q; }
        float mu = s * (1.0f/1024.0f);
        float ri = rsqrtf(q * (1.0f/1024.0f) - mu*mu + 1e-5f);
        #pragma unroll
        for (int i = 0; i < 8; i++){
            acc[i].x += (v[i].x-mu)*ri; acc[i].y += (v[i].y-mu)*ri;
            acc[i].z += (v[i].z-mu)*ri; acc[i].w += (v[i].w-mu)*ri;
            // fp16 split of 32*x
            union { __half h[4]; uint2 u; } ph, pl;
            float sx = v[i].x*32.f, sy = v[i].y*32.f, sz = v[i].z*32.f, sw = v[i].w*32.f;
            ph.h[0] = __float2half_rn(sx); pl.h[0] = __float2half_rn(sx - __half2float(ph.h[0]));
            ph.h[1] = __float2half_rn(sy); pl.h[1] = __float2half_rn(sy - __half2float(ph.h[1]));
            ph.h[2] = __float2half_rn(sz); pl.h[2] = __float2half_rn(sz - __half2float(ph.h[2]));
            ph.h[3] = __float2half_rn(sw); pl.h[3] = __float2half_rn(sw - __half2float(ph.h[3]));
            *(uint2*)(d_Xh + (size_t)t*1024 + i*128 + lane*4) = ph.u;
            *(uint2*)(d_Xl + (size_t)t*1024 + i*128 + lane*4) = pl.u;
        }
    }
    #pragma unroll
    for (int i = 0; i < 8; i++)
        *(float4*)(d_partial + (size_t)gw*1024 + i*128 + lane*4) = acc[i];
}

// 8 threads per output; 2048 warp-rows = 256 rows per batch.
__global__ void k_pool_fin(const float* __restrict__ gp, const float* __restrict__ bp){
    __shared__ float red[256];
    const int tid = threadIdx.x;            // 256; grid 256; 32 outputs/block
    const int o  = blockIdx.x*32 + (tid >> 3);   // 0..8191
    const int pt = tid & 7;
    const int b = o >> 10, d = o & 1023;
    float s = 0.f;
    #pragma unroll 8
    for (int p = pt; p < 256; p += 8) s += d_partial[(size_t)(b*256 + p)*1024 + d];
    red[tid] = s;
    __syncthreads();
    if (pt == 0){
        float t = 0.f;
        #pragma unroll
        for (int q = 0; q < 8; q++) t += red[tid + q];
        d_g[o] = (t * (1.0f/(float)Sq)) * gp[d] + bp[d];
    }
}

// ---------------- 2) timestep embedding
__global__ void k_emb(const int* __restrict__ step){
    int i = blockIdx.x*256 + threadIdx.x;
    if (i >= Bq*DCq) return;
    int j = i & (DCq-1);
    int si = *step; if (si > 31) si = 31; if (si < 0) si = 0;
    float t = (float)si / 31.0f;
    float sig = cosf(t * 1.57079632679489662f);
    if (sig < 1e-4f) sig = 1e-4f;
    const int half = DCq/2;
    int f = (j < half) ? j : j - half;
    float freq = expf(-logf(10000.0f) * (float)f / (float)half);
    float a = sig * freq;
    d_emb[i] = (j < half) ? cosf(a) : sinf(a);
}

// ---------------- 3) split-K skinny GEMM, float4 weight loads
// 256 threads; thread owns 4 consecutive n; grid (N/1024, KS); Kc = K/KS <= 32.
template<int ACT_IN>
__global__ void k_gemm8p(const float* __restrict__ A, const float* __restrict__ scale,
                         const float* __restrict__ W, float* __restrict__ part,
                         int K, int N, int KS){
    __shared__ float sA[8][32];
    const int tid = threadIdx.x;                 // 256
    const int n0  = blockIdx.x*1024 + tid*4;
    const int ks  = blockIdx.y;
    const int Kc  = K / KS;                      // 8, 16, or 32
    const int k0  = ks * Kc;
    if (tid < 8*Kc){
        int i = tid / Kc, k = tid % Kc;          // Kc is a power of two
        float v = A[(size_t)i*K + k0 + k];
        if (ACT_IN) v = gelu_f(v);
        if (scale)  v *= scale[k0 + k];
        sA[i][k] = v;
    }
    __syncthreads();
    float4 acc[8];
    #pragma unroll
    for (int bb = 0; bb < 8; bb++) acc[bb] = make_float4(0.f,0.f,0.f,0.f);
    #pragma unroll 8
    for (int k = 0; k < Kc; k++){
        float4 w = *(const float4*)(W + (size_t)(k0 + k)*N + n0);
        #pragma unroll
        for (int bb = 0; bb < 8; bb++){
            float a = sA[bb][k];
            acc[bb].x += a*w.x; acc[bb].y += a*w.y;
            acc[bb].z += a*w.z; acc[bb].w += a*w.w;
        }
    }
    float* p = part + (size_t)ks*8*N;
    #pragma unroll
    for (int bb = 0; bb < 8; bb++)
        *(float4*)(p + (size_t)bb*N + n0) = acc[bb];
}

// finisher: 8 threads per output; grid = 8N/32 blocks of 256.
template<int ACT_OUT>
__global__ void k_gemm8f(const float* __restrict__ part, const float* __restrict__ bias,
                         float* __restrict__ out, int N, int KS){
    __shared__ float red[256];
    const int tid = threadIdx.x;
    const int o  = blockIdx.x*32 + (tid >> 3);   // 0..8N-1
    const int pt = tid & 7;
    float s = 0.f;
    #pragma unroll 4
    for (int p = pt; p < KS; p += 8) s += part[(size_t)p*8*N + o];
    red[tid] = s;
    __syncthreads();
    if (pt == 0){
        float t = 0.f;
        #pragma unroll
        for (int q = 0; q < 8; q++) t += red[tid + q];
        if (bias) t += bias[o % N];
        if (ACT_OUT) t = gelu_f(t);
        out[o] = t;
    }
}

// ---------------- 4) small elementwise / LN helpers
__device__ __forceinline__ float2 blockReduce2(float s, float q, volatile float* red, int tid){
    #pragma unroll
    for (int o = 16; o > 0; o >>= 1){
        s += __shfl_down_sync(0xffffffffu, s, o);
        q += __shfl_down_sync(0xffffffffu, q, o);
    }
    if ((tid & 31) == 0){ red[tid>>5] = s; red[8 + (tid>>5)] = q; }
    __syncthreads();
    float S = red[0]+red[1]+red[2]+red[3]+red[4]+red[5]+red[6]+red[7];
    float Q = red[8]+red[9]+red[10]+red[11]+red[12]+red[13]+red[14]+red[15];
    __syncthreads();
    return make_float2(S, Q);
}

__global__ void k_concat(){
    int i = blockIdx.x*256 + threadIdx.x;
    if (i >= Bq*2*DCq) return;
    int b = i >> 11, k = i & 2047;
    d_condin[i] = (k < 1024) ? d_xctrl[(b<<10)+k] : d_tembed[(b<<10)+k-1024];
}

__global__ void k_copy_z(const float* __restrict__ z){
    int i = blockIdx.x*256 + threadIdx.x;
    if (i < Bq*DCq) d_zcur[i] = z[i];
}

__global__ void k_adaln1(){
    __shared__ float red[16];
    const int b = blockIdx.x, tid = threadIdx.x;
    float4 v = ((const float4*)(d_zcur + (b<<10)))[tid];
    float2 r = blockReduce2(v.x+v.y+v.z+v.w, v.x*v.x+v.y*v.y+v.z*v.z+v.w*v.w, red, tid);
    float mu = r.x*(1.0f/1024.0f);
    float ri = rsqrtf(r.y*(1.0f/1024.0f) - mu*mu + 1e-5f);
    const float* mod = d_mod + b*4096;
    int j = tid << 2;
    float4 s1 = *(const float4*)(mod + j);
    float4 h1 = *(const float4*)(mod + 1024 + j);
    float4 o;
    o.x = (v.x-mu)*ri*(1.0f+s1.x)+h1.x;
    o.y = (v.y-mu)*ri*(1.0f+s1.y)+h1.y;
    o.z = (v.z-mu)*ri*(1.0f+s1.z)+h1.z;
    o.w = (v.w-mu)*ri*(1.0f+s1.w)+h1.w;
    ((float4*)(d_h + (b<<10)))[tid] = o;
}

__global__ void k_adaln2(){
    int i = blockIdx.x*256 + threadIdx.x;
    if (i >= Bq*DCq) return;
    int b = i >> 10, j = i & 1023;
    float s2  = d_mod[b*4096 + 2048 + j];
    float sh2 = d_mod[b*4096 + 3072 + j];
    d_zcur[i] += d_h3[i]*(1.0f+s2) + sh2;
}

__global__ void k_lnz(const float* __restrict__ gz, const float* __restrict__ bz){
    __shared__ float red[16];
    const int b = blockIdx.x, tid = threadIdx.x;
    float4 v = ((const float4*)(d_zf + (b<<10)))[tid];
    float2 r = blockReduce2(v.x+v.y+v.z+v.w, v.x*v.x+v.y*v.y+v.z*v.z+v.w*v.w, red, tid);
    float mu = r.x*(1.0f/1024.0f);
    float ri = rsqrtf(r.y*(1.0f/1024.0f) - mu*mu + 1e-5f);
    int j = tid << 2;
    float4 g4 = *(const float4*)(gz + j);
    float4 b4 = *(const float4*)(bz + j);
    float4 y;
    y.x = (v.x-mu)*ri*g4.x + b4.x;
    y.y = (v.y-mu)*ri*g4.y + b4.y;
    y.z = (v.z-mu)*ri*g4.z + b4.z;
    y.w = (v.w-mu)*ri*g4.w + b4.w;
    ((float4*)(d_zfinal + (b<<10)))[tid] = y;
    float2 r2 = blockReduce2(y.x+y.y+y.z+y.w, y.x*y.x+y.y*y.y+y.z*y.z+y.w*y.w, red, tid);
    if (tid == 0){ d_Sz[b] = r2.x; d_Qz[b] = r2.y; }
}

// ---------------- 5) router weight prep: col sums Ag/Abr + fp16 split of (64*gr*Wr1_x)^T
__global__ void k_prep_w(const float* __restrict__ Wr1, const float* __restrict__ gr,
                         const float* __restrict__ br){
    const int tid = threadIdx.x;            // 256, float4 over 1024 cols (j = tid*4..+3)
    const int r0 = blockIdx.x << 3;         // 256 blocks x 8 k-rows
    float4 ag = make_float4(0,0,0,0), ab = make_float4(0,0,0,0);
    union { __half h[8]; int4 v; } wh[4], wl[4];
    #pragma unroll
    for (int rr = 0; rr < 8; rr++){
        int k = r0 + rr;
        float4 w = ((const float4*)(Wr1 + (size_t)k*1024))[tid];
        float gk = gr[k], bk = br[k];
        ag.x += gk*w.x; ag.y += gk*w.y; ag.z += gk*w.z; ag.w += gk*w.w;
        ab.x += bk*w.x; ab.y += bk*w.y; ab.z += bk*w.z; ab.w += bk*w.w;
        if (r0 < 1024){
            float s0 = 64.f*gk*w.x, s1 = 64.f*gk*w.y, s2 = 64.f*gk*w.z, s3 = 64.f*gk*w.w;
            wh[0].h[rr] = __float2half_rn(s0); wl[0].h[rr] = __float2half_rn(s0 - __half2float(wh[0].h[rr]));
            wh[1].h[rr] = __float2half_rn(s1); wl[1].h[rr] = __float2half_rn(s1 - __half2float(wh[1].h[rr]));
            wh[2].h[rr] = __float2half_rn(s2); wl[2].h[rr] = __float2half_rn(s2 - __half2float(wh[2].h[rr]));
            wh[3].h[rr] = __float2half_rn(s3); wl[3].h[rr] = __float2half_rn(s3 - __half2float(wh[3].h[rr]));
        }
    }
    if (r0 < 1024){
        #pragma unroll
        for (int jj = 0; jj < 4; jj++){
            *(int4*)(d_WgTh + (size_t)(tid*4 + jj)*1024 + r0) = wh[jj].v;
            *(int4*)(d_WgTl + (size_t)(tid*4 + jj)*1024 + r0) = wl[jj].v;
        }
    }
    ((float4*)(d_AgP  + (size_t)blockIdx.x*1024))[tid] = ag;
    ((float4*)(d_AbrP + (size_t)blockIdx.x*1024))[tid] = ab;
}

__global__ void k_prep_w2(){
    __shared__ float sa[256], sb[256];
    const int tid = threadIdx.x;            // 256; grid 32; 8 threads per output col
    const int j = blockIdx.x*32 + (tid >> 3);
    const int part = tid & 7;
    float a = 0.f, c = 0.f;
    for (int p = part; p < 256; p += 8){ a += d_AgP[p*1024 + j]; c += d_AbrP[p*1024 + j]; }
    sa[tid] = a; sb[tid] = c;
    __syncthreads();
    if (part == 0){
        float A = 0.f, C = 0.f;
        #pragma unroll
        for (int q = 0; q < 8; q++){ A += sa[tid+q]; C += sb[tid+q]; }
        d_Ag[j] = A; d_Abr[j] = C;
    }
}

// ---------------- 6) router GEMM on legacy HMMA, fp16 2-way split, cp.async 3-stage pipe.
#define LDA 40                    // halves per smem row (32 + 8 pad)
#define ARR_SZ 10240              // one operand array: 128*LDA*2 bytes
#define STAGE_SZ (4*ARR_SZ)       // 40960: AH, AL, BH, BL
#define NSTAGE 3
#define OFF_W2 (NSTAGE*STAGE_SZ)          // 122880: Wr2 slice [128][16] floats (8 KB)
#define OFF_CZ (OFF_W2 + 8192)            // 131072
#define OFF_CG (OFF_CZ + 512)
#define OFF_CE (OFF_CG + 512)
#define RSM_TOTAL (OFF_CE + 512)          // 132608

__global__ void __launch_bounds__(256, 1) k_router_mma(const float* __restrict__ br1,
                                                       const float* __restrict__ Wr2){
    extern __shared__ __align__(16) char sm[];
    const uint32_t smb = smem_u32(sm);
    const int tid   = threadIdx.x;
    const int wid   = tid >> 5;
    const int lane  = tid & 31;
    const int warpM = wid & 3;          // 0..3
    const int warpN = wid >> 2;         // 0..1
    const int jn0   = blockIdx.x * 128; // N block (0..7)
    const int t0    = blockIdx.y * 128; // M block (0..255)
    const int b     = t0 >> 12;

    // stage Wr2 slice + epilogue constants
    {
        const float* w2g = Wr2 + (size_t)jn0*16;
        float* w2s = (float*)(sm + OFF_W2);
        *(float4*)(w2s + tid*8)     = *(const float4*)(w2g + tid*8);
        *(float4*)(w2s + tid*8 + 4) = *(const float4*)(w2g + tid*8 + 4);
        if (tid < 128){
            ((float*)(sm + OFF_CZ))[tid] = d_azg[(b<<10) + jn0 + tid];
            ((float*)(sm + OFF_CG))[tid] = d_Ag[jn0 + tid];
            ((float*)(sm + OFF_CE))[tid] = d_Abr[jn0 + tid] + br1[jn0 + tid];
        }
    }

    const int ld_r0 = tid >> 2;               // rows for q=0 / q=1: ld_r0, ld_r0+64
    const int ld_c  = (tid & 3) * 8;          // half offset within 32-half row

    float acc[2][8][4];
    #pragma unroll
    for (int mt = 0; mt < 2; mt++)
        #pragma unroll
        for (int nt = 0; nt < 8; nt++)
            #pragma unroll
            for (int e = 0; e < 4; e++) acc[mt][nt][e] = 0.0f;

    #pragma unroll
    for (int pc = 0; pc < 2; pc++){
        const int kk = pc*32;
        const uint32_t sb = smb + pc*STAGE_SZ;
        #pragma unroll
        for (int q = 0; q < 2; q++){
            int row = ld_r0 + q*64;
            uint32_t so = (uint32_t)(row*LDA + ld_c)*2;
            size_t goA = (size_t)(t0  + row)*1024 + kk + ld_c;
            size_t goB = (size_t)(jn0 + row)*1024 + kk + ld_c;
            cpa16(sb + so,            d_Xh   + goA);
            cpa16(sb + ARR_SZ + so,   d_Xl   + goA);
            cpa16(sb + 2*ARR_SZ + so, d_WgTh + goB);
            cpa16(sb + 3*ARR_SZ + so, d_WgTl + goB);
        }
        CP_COMMIT();
    }

    for (int it = 0; it < 32; it++){
        CP_WAIT1();
        __syncthreads();
        if (it + 2 < 32){
            const int kk = (it+2)*32;
            const uint32_t sb = smb + ((it+2)%NSTAGE)*STAGE_SZ;
            #pragma unroll
            for (int q = 0; q < 2; q++){
                int row = ld_r0 + q*64;
                uint32_t so = (uint32_t)(row*LDA + ld_c)*2;
                size_t goA = (size_t)(t0  + row)*1024 + kk + ld_c;
                size_t goB = (size_t)(jn0 + row)*1024 + kk + ld_c;
                cpa16(sb + so,            d_Xh   + goA);
                cpa16(sb + ARR_SZ + so,   d_Xl   + goA);
                cpa16(sb + 2*ARR_SZ + so, d_WgTh + goB);
                cpa16(sb + 3*ARR_SZ + so, d_WgTl + goB);
            }
        }
        CP_COMMIT();

        const uint32_t cb = smb + (it%NSTAGE)*STAGE_SZ;
        #pragma unroll
        for (int kh = 0; kh < 2; kh++){
            uint32_t ah[2][4], al[2][4], bh[8][2], bl[8][2];
            const int colh = (lane >> 4)*8 + kh*16;
            #pragma unroll
            for (int mt = 0; mt < 2; mt++){
                uint32_t ra = (uint32_t)((warpM*32 + mt*16 + (lane & 15))*LDA + colh)*2;
                ldsm4(ah[mt], cb + ra);
                ldsm4(al[mt], cb + ARR_SZ + ra);
            }
            #pragma unroll
            for (int p = 0; p < 4; p++){
                uint32_t rb = (uint32_t)((warpN*64 + p*16 + (lane & 15))*LDA + colh)*2;
                uint32_t q4[4];
                ldsm4(q4, cb + 2*ARR_SZ + rb);
                bh[2*p][0] = q4[0]; bh[2*p][1] = q4[2];
                bh[2*p+1][0] = q4[1]; bh[2*p+1][1] = q4[3];
                ldsm4(q4, cb + 3*ARR_SZ + rb);
                bl[2*p][0] = q4[0]; bl[2*p][1] = q4[2];
                bl[2*p+1][0] = q4[1]; bl[2*p+1][1] = q4[3];
            }
            #pragma unroll
            for (int mt = 0; mt < 2; mt++)
                #pragma unroll
                for (int nt = 0; nt < 8; nt++){
                    mma16816(acc[mt][nt], ah[mt], bh[nt]);
                    mma16816(acc[mt][nt], ah[mt], bl[nt]);
                    mma16816(acc[mt][nt], al[mt], bh[nt]);
                }
        }
    }
    __syncthreads();   // staging smem now reused as per-warp gelu slabs

    const float INV = 1.0f/2048.0f;
    const float Szb = d_Sz[b], Qzb = d_Qz[b];
    const float* czs = (const float*)(sm + OFF_CZ);
    const float* cgs = (const float*)(sm + OFF_CG);
    const float* ces = (const float*)(sm + OFF_CE);
    float* gslab = (float*)(sm) + wid*1088;            // [16][68] floats per warp
    const int g8 = lane >> 2;
    const int t2 = lane & 3;
    const int slice = blockIdx.x*2 + warpN;             // 0..15
    const float* w2s = (const float*)(sm + OFF_W2);

    #pragma unroll
    for (int mt = 0; mt < 2; mt++){
        int tA = t0 + warpM*32 + mt*16 + g8;
        int tB = tA + 8;
        float muA  = (d_Sx[tA] + Szb) * (1.0f/2048.0f);
        float riA  = rsqrtf((d_Qx[tA] + Qzb) * (1.0f/2048.0f) - muA*muA + 1e-5f);
        float mriA = muA * riA;
        float muB  = (d_Sx[tB] + Szb) * (1.0f/2048.0f);
        float riB  = rsqrtf((d_Qx[tB] + Qzb) * (1.0f/2048.0f) - muB*muB + 1e-5f);
        float mriB = muB * riB;
        #pragma unroll
        for (int nt = 0; nt < 8; nt++){
            int jl0 = warpN*64 + nt*8 + t2*2;
            float c0z = czs[jl0],   c0g = cgs[jl0],   c0e = ces[jl0];
            float c1z = czs[jl0+1], c1g = cgs[jl0+1], c1e = ces[jl0+1];
            float gA0 = gelu_f((acc[mt][nt][0]*INV + c0z)*riA - mriA*c0g + c0e);
            float gA1 = gelu_f((acc[mt][nt][1]*INV + c1z)*riA - mriA*c1g + c1e);
            float gB0 = gelu_f((acc[mt][nt][2]*INV + c0z)*riB - mriB*c0g + c0e);
            float gB1 = gelu_f((acc[mt][nt][3]*INV + c1z)*riB - mriB*c1g + c1e);
            int cl = nt*8 + t2*2;
            gslab[g8*68 + cl]       = gA0;
            gslab[g8*68 + cl + 1]   = gA1;
            gslab[(g8+8)*68 + cl]     = gB0;
            gslab[(g8+8)*68 + cl + 1] = gB1;
        }
        __syncwarp();
        {
            int r  = lane & 15;
            int hs = lane >> 4;
            float pl[8] = {0,0,0,0,0,0,0,0};
            #pragma unroll 8
            for (int k = 0; k < 64; k++){
                float gv = gslab[r*68 + k];
                const float* w2 = w2s + (warpN*64 + k)*16 + hs*8;
                float4 wa = *(const float4*)(w2);
                float4 wb = *(const float4*)(w2 + 4);
                pl[0] += gv*wa.x; pl[1] += gv*wa.y; pl[2] += gv*wa.z; pl[3] += gv*wa.w;
                pl[4] += gv*wb.x; pl[5] += gv*wb.y; pl[6] += gv*wb.z; pl[7] += gv*wb.w;
            }
            int tok = t0 + warpM*32 + mt*16 + r;
            float* op = d_plog + ((size_t)slice*NT + tok)*16 + hs*8;
            *(float4*)op       = make_float4(pl[0], pl[1], pl[2], pl[3]);
            *(float4*)(op + 4) = make_float4(pl[4], pl[5], pl[6], pl[7]);
        }
        __syncwarp();
    }
}

// ---------------- 7) router tail: reduce partial logits, + br2, softmax top-2 renorm
__global__ void k_router2(const float* __restrict__ br2, float* __restrict__ out){
    int t = blockIdx.x*256 + threadIdx.x;   // 128 blocks
    if (t >= NT) return;
    float lg[16];
    #pragma unroll
    for (int h = 0; h < 16; h++) lg[h] = br2[h];
    #pragma unroll
    for (int s = 0; s < 16; s++){
        const float4* p = (const float4*)(d_plog + ((size_t)s*NT + t)*16);
        float4 a = p[0], bq = p[1], c = p[2], d = p[3];
        lg[0]+=a.x; lg[1]+=a.y; lg[2]+=a.z; lg[3]+=a.w;
        lg[4]+=bq.x; lg[5]+=bq.y; lg[6]+=bq.z; lg[7]+=bq.w;
        lg[8]+=c.x; lg[9]+=c.y; lg[10]+=c.z; lg[11]+=c.w;
        lg[12]+=d.x; lg[13]+=d.y; lg[14]+=d.z; lg[15]+=d.w;
    }
    int i1 = 0; float v1 = lg[0];
    #pragma unroll
    for (int h = 1; h < 16; h++) if (lg[h] > v1){ v1 = lg[h]; i1 = h; }
    int i2 = -1; float v2 = -3.4e38f;
    #pragma unroll
    for (int h = 0; h < 16; h++) if (h != i1 && lg[h] > v2){ v2 = lg[h]; i2 = h; }
    float e2 = expf(v2 - v1);
    float den = 1.0f + e2;
    float o1 = 1.0f/den, o2 = e2/den;
    float* op = out + (size_t)t*16;
    #pragma unroll
    for (int h = 0; h < 16; h++) op[h] = (h == i1) ? o1 : ((h == i2) ? o2 : 0.0f);
}

// ---------------- launch ----------------
static float* symPtr(const void* sym){
    void* p = nullptr;
    cudaGetSymbolAddress(&p, sym);
    return (float*)p;
}

extern "C" void kernel_launch(void* const* d_in, const int* in_sizes, int n_in,
                              void* d_out, int out_size){
    (void)in_sizes; (void)n_in; (void)out_size;
    const float* X      = (const float*)d_in[0];
    const float* z      = (const float*)d_in[1];
    const int*   step   = (const int*)  d_in[2];
    const float* g_pool = (const float*)d_in[3];
    const float* b_pool = (const float*)d_in[4];
    const float* W_inp  = (const float*)d_in[5];
    const float* b_inp  = (const float*)d_in[6];
    const float* Wt1    = (const float*)d_in[7];
    const float* bt1    = (const float*)d_in[8];
    const float* Wt2    = (const float*)d_in[9];
    const float* bt2    = (const float*)d_in[10];
    const float* Wc1    = (const float*)d_in[11];
    const float* bc1    = (const float*)d_in[12];
    const float* Wc2    = (const float*)d_in[13];
    const float* bc2    = (const float*)d_in[14];
    const float* W_mod  = (const float*)d_in[15];
    const float* b_mod  = (const float*)d_in[16];
    const float* Wm1    = (const float*)d_in[17];
    const float* bm1    = (const float*)d_in[18];
    const float* Wm2    = (const float*)d_in[19];
    const float* bm2    = (const float*)d_in[20];
    const float* Wf     = (const float*)d_in[21];
    const float* bf     = (const float*)d_in[22];
    const float* gz     = (const float*)d_in[23];
    const float* bz     = (const float*)d_in[24];
    const float* gr     = (const float*)d_in[25];
    const float* br     = (const float*)d_in[26];
    const float* Wr1    = (const float*)d_in[27];
    const float* br1    = (const float*)d_in[28];
    const float* Wr2    = (const float*)d_in[29];
    const float* br2    = (const float*)d_in[30];
    float* out = (float*)d_out;

    float* p_g      = symPtr(d_g);
    float* p_xctrl  = symPtr(d_xctrl);
    float* p_emb    = symPtr(d_emb);
    float* p_tmpA   = symPtr(d_tmpA);
    float* p_tembed = symPtr(d_tembed);
    float* p_condin = symPtr(d_condin);
    float* p_cond   = symPtr(d_cond);
    float* p_h      = symPtr(d_h);
    float* p_zcur   = symPtr(d_zcur);
    float* p_zf     = symPtr(d_zf);
    float* p_zfinal = symPtr(d_zfinal);
    float* p_azg    = symPtr(d_azg);
    float* p_pp     = symPtr(d_pp);

    static int smem_set = 0;
    if (!smem_set){
        cudaFuncSetAttribute(k_router_mma, cudaFuncAttributeMaxDynamicSharedMemorySize,
                             RSM_TOTAL);
        smem_set = 1;
    }

    // pool path (also produces per-token Sx/Qx + fp16 splits of X)
    k_pool<<<256, 256>>>(X);
    k_pool_fin<<<256, 256>>>(g_pool, b_pool);

    // router weight prep (independent of the rest)
    k_prep_w<<<256, 256>>>(Wr1, gr, br);
    k_prep_w2<<<32, 256>>>();

    // x_ctrl = g @ W_inp + b_inp            (K=1024, N=1024, KS=128)
    k_gemm8p<0><<<dim3(1, 128), 256>>>(p_g, nullptr, W_inp, p_pp, 1024, 1024, 128);
    k_gemm8f<0><<<256, 256>>>(p_pp, b_inp, p_xctrl, 1024, 128);

    // timestep embedding MLP
    k_emb<<<32, 256>>>(step);
    k_gemm8p<0><<<dim3(4, 32), 256>>>(p_emb, nullptr, Wt1, p_pp, 1024, 4096, 32);
    k_gemm8f<1><<<1024, 256>>>(p_pp, bt1, p_tmpA, 4096, 32);
    k_gemm8p<0><<<dim3(1, 128), 256>>>(p_tmpA, nullptr, Wt2, p_pp, 4096, 1024, 128);
    k_gemm8f<0><<<256, 256>>>(p_pp, bt2, p_tembed, 1024, 128);

    // cond fusion
    k_concat<<<64, 256>>>();
    k_gemm8p<0><<<dim3(1, 128), 256>>>(p_condin, nullptr, Wc1, p_pp, 2048, 1024, 128);
    k_gemm8f<1><<<256, 256>>>(p_pp, bc1, p_tmpA, 1024, 128);
    k_gemm8p<0><<<dim3(1, 128), 256>>>(p_tmpA, nullptr, Wc2, p_pp, 1024, 1024, 128);
    k_gemm8f<0><<<256, 256>>>(p_pp, bc2, p_cond, 1024, 128);

    // adaLN denoise blocks
    k_copy_z<<<32, 256>>>(z);
    for (int l = 0; l < 2; l++){
        k_gemm8p<1><<<dim3(4, 32), 256>>>(p_cond, nullptr, W_mod + (size_t)l*1024*4096,
                                          p_pp, 1024, 4096, 32);
        k_gemm8f<0><<<1024, 256>>>(p_pp, b_mod + (size_t)l*4096, symPtr(d_mod), 4096, 32);
        k_adaln1<<<8, 256>>>();
        k_gemm8p<0><<<dim3(4, 32), 256>>>(p_h, nullptr, Wm1 + (size_t)l*1024*4096,
                                          p_pp, 1024, 4096, 32);
        k_gemm8f<0><<<1024, 256>>>(p_pp, bm1 + (size_t)l*4096, p_tmpA, 4096, 32);
        k_gemm8p<1><<<dim3(1, 128), 256>>>(p_tmpA, nullptr, Wm2 + (size_t)l*4096*1024,
                                           p_pp, 4096, 1024, 128);
        k_gemm8f<0><<<256, 256>>>(p_pp, bm2 + (size_t)l*1024, symPtr(d_h3), 1024, 128);
        k_adaln2<<<32, 256>>>();
    }

    // final projection + LN
    k_gemm8p<0><<<dim3(1, 128), 256>>>(p_zcur, nullptr, Wf, p_pp, 1024, 1024, 128);
    k_gemm8f<0><<<256, 256>>>(p_pp, bf, p_zf, 1024, 128);
    k_lnz<<<8, 256>>>(gz, bz);
    k_gemm8p<0><<<dim3(1, 128), 256>>>(p_zfinal, gr + 1024, Wr1 + (size_t)1024*1024,
                                       p_pp, 1024, 1024, 128);
    k_gemm8f<0><<<256, 256>>>(p_pp, nullptr, p_azg, 1024, 128);

    // router: pipelined HMMA GEMM + fused LN fixup/gelu/Wr2 partials, then tiny reduce
    k_router_mma<<<dim3(8, 256), 256, RSM_TOTAL>>>(br1, Wr2);
    k_router2<<<128, 256>>>(br2, out);
}